// round 7
// baseline (speedup 1.0000x reference)
#include <cuda_runtime.h>
#include <math.h>

// Problem constants (fixed shapes from reference)
#define BATCH  8
#define C_IN   256
#define NPIX   1024   // 32*32
#define INNER  512    // heads*dim_head
#define HEADS  8
#define DH     64
#define KCONV  2304   // 256*9
#define MKV    1024   // 2*INNER

// Scratch (static device globals — no allocation allowed)
__device__ float g_Q [(size_t)BATCH * INNER * NPIX];   // [b][h*64+d][p]
__device__ float g_KV[(size_t)BATCH * MKV   * NPIX];   // [b][co][p], co<512: K, co>=512: V
__device__ float g_AO[(size_t)BATCH * INNER * NPIX];   // gelu(attention out), [b][h*64+d][p]

// ---------------------------------------------------------------------------
// Generic tiled GEMM for 1x1 convs:
//   C[z][m][n] = sum_k A[m][k] * B[z][k][n]  (+ bias[m])
// Tile 64x64, BK=16, 256 threads, 4x4 per thread.
// ---------------------------------------------------------------------------
template<int BIAS>
__global__ __launch_bounds__(256)
void gemm_1x1(const float* __restrict__ A, const float* __restrict__ Bm,
              float* __restrict__ Cm, const float* __restrict__ bias,
              int M, int N, int K)
{
    __shared__ float sA[16][65];
    __shared__ float sB[16][65];
    const int t  = threadIdx.x;
    const int tx = t & 15, ty = t >> 4;
    const int n0 = blockIdx.x * 64, m0 = blockIdx.y * 64;
    const float* Bp = Bm + (size_t)blockIdx.z * K * N;
    float*       Cp = Cm + (size_t)blockIdx.z * M * N;

    float acc[4][4] = {};
    for (int k0 = 0; k0 < K; k0 += 16) {
        #pragma unroll
        for (int r = 0; r < 4; r++) {
            int idx = t + r * 256;
            { int kk = idx & 15, m = idx >> 4;
              sA[kk][m] = A[(size_t)(m0 + m) * K + k0 + kk]; }
            { int nn = idx & 63, kk = idx >> 6;
              sB[kk][nn] = Bp[(size_t)(k0 + kk) * N + n0 + nn]; }
        }
        __syncthreads();
        #pragma unroll
        for (int kk = 0; kk < 16; kk++) {
            float a[4], b[4];
            #pragma unroll
            for (int i = 0; i < 4; i++) a[i] = sA[kk][ty * 4 + i];
            #pragma unroll
            for (int j = 0; j < 4; j++) b[j] = sB[kk][tx * 4 + j];
            #pragma unroll
            for (int i = 0; i < 4; i++)
                #pragma unroll
                for (int j = 0; j < 4; j++)
                    acc[i][j] = fmaf(a[i], b[j], acc[i][j]);
        }
        __syncthreads();
    }
    #pragma unroll
    for (int i = 0; i < 4; i++) {
        int m = m0 + ty * 4 + i;
        float bv = BIAS ? bias[m] : 0.f;
        #pragma unroll
        for (int j = 0; j < 4; j++)
            Cp[(size_t)m * N + n0 + tx * 4 + j] = acc[i][j] + bv;
    }
}

// ---------------------------------------------------------------------------
// 3x3 conv (pad=1) as implicit GEMM:
//   KV[b][co][p] = sum_{k=ci*9+tap} W[co][k] * X[b][ci][shift_tap(p)]
// M=1024, N=1024, K=2304. Same 64x64 tile scheme; B-tile load does the
// im2col gather with boundary predication.
// ---------------------------------------------------------------------------
__global__ __launch_bounds__(256)
void conv3x3_kv(const float* __restrict__ W, const float* __restrict__ X)
{
    __shared__ float sA[16][65];
    __shared__ float sB[16][65];
    const int t  = threadIdx.x;
    const int tx = t & 15, ty = t >> 4;
    const int n0 = blockIdx.x * 64, m0 = blockIdx.y * 64;
    const float* Xp = X    + (size_t)blockIdx.z * C_IN * NPIX;
    float*       Cp = g_KV + (size_t)blockIdx.z * MKV  * NPIX;

    float acc[4][4] = {};
    for (int k0 = 0; k0 < KCONV; k0 += 16) {
        #pragma unroll
        for (int r = 0; r < 4; r++) {
            int idx = t + r * 256;
            { int kk = idx & 15, m = idx >> 4;
              sA[kk][m] = W[(size_t)(m0 + m) * KCONV + k0 + kk]; }
            { int nn = idx & 63, kk = idx >> 6;
              int kg  = k0 + kk;
              int ci  = kg / 9;
              int tap = kg - ci * 9;
              int dy  = tap / 3 - 1;
              int dx  = tap - (tap / 3) * 3 - 1;
              int n   = n0 + nn;
              int y   = (n >> 5) + dy;
              int x   = (n & 31) + dx;
              float v = 0.f;
              if ((unsigned)y < 32u && (unsigned)x < 32u)
                  v = Xp[(size_t)ci * NPIX + (y << 5) + x];
              sB[kk][nn] = v; }
        }
        __syncthreads();
        #pragma unroll
        for (int kk = 0; kk < 16; kk++) {
            float a[4], b[4];
            #pragma unroll
            for (int i = 0; i < 4; i++) a[i] = sA[kk][ty * 4 + i];
            #pragma unroll
            for (int j = 0; j < 4; j++) b[j] = sB[kk][tx * 4 + j];
            #pragma unroll
            for (int i = 0; i < 4; i++)
                #pragma unroll
                for (int j = 0; j < 4; j++)
                    acc[i][j] = fmaf(a[i], b[j], acc[i][j]);
        }
        __syncthreads();
    }
    #pragma unroll
    for (int i = 0; i < 4; i++) {
        int m = m0 + ty * 4 + i;
        #pragma unroll
        for (int j = 0; j < 4; j++)
            Cp[(size_t)m * NPIX + n0 + tx * 4 + j] = acc[i][j];
    }
}

// ---------------------------------------------------------------------------
// Flash attention (fp32, exact): one CTA per (b*h, 64-query tile).
// n=1024 keys, d=64. Online softmax, O accumulator in registers (4x4/thread).
// GELU (exact, erf) fused into epilogue; coalesced writeback via smem stage.
// ---------------------------------------------------------------------------
#define FA_SMEM_FLOATS (4 * 64 * 65 + 3 * 64)

__global__ __launch_bounds__(256)
void flash_attn(const float* __restrict__ Q, const float* __restrict__ KV,
                float* __restrict__ AO)
{
    extern __shared__ float sm[];
    float* sQ = sm;               // [64][65]
    float* sK = sQ + 64 * 65;     // [64][65]
    float* sV = sK + 64 * 65;     // [64][65]
    float* sS = sV + 64 * 65;     // [64][65]
    float* rm = sS + 64 * 65;     // [64] running max
    float* rl = rm + 64;          // [64] running denom
    float* rf = rl + 64;          // [64] rescale factor

    const int t  = threadIdx.x;
    const int tx = t & 15, ty = t >> 4;
    const int q0 = blockIdx.x * 64;
    const int bh = blockIdx.y;
    const int b  = bh >> 3, h = bh & 7;

    const float* qb = Q  + ((size_t)b * INNER + h * DH) * NPIX;
    const float* kb = KV + ((size_t)b * MKV   + h * DH) * NPIX;
    const float* vb = KV + ((size_t)b * MKV + INNER + h * DH) * NPIX;
    float*       ob = AO + ((size_t)b * INNER + h * DH) * NPIX;

    // Load Q tile: sQ[qi][d]  (coalesced over p, conflict-free stride-65 store)
    for (int idx = t; idx < 4096; idx += 256) {
        int d = idx >> 6, qi = idx & 63;
        sQ[qi * 65 + d] = qb[(size_t)d * NPIX + q0 + qi];
    }
    if (t < 64) { rm[t] = -1e30f; rl[t] = 0.f; }

    float O[4][4] = {};
    const float scale = 0.125f;  // 64^-0.5

    for (int k0 = 0; k0 < NPIX; k0 += 64) {
        for (int idx = t; idx < 4096; idx += 256) {
            int d = idx >> 6, ki = idx & 63;
            sK[ki * 65 + d] = kb[(size_t)d * NPIX + k0 + ki];
            sV[ki * 65 + d] = vb[(size_t)d * NPIX + k0 + ki];
        }
        __syncthreads();

        // S = scale * Q K^T  (64x64 tile, regs)
        float s[4][4] = {};
        #pragma unroll 8
        for (int d = 0; d < 64; d++) {
            float a[4], k[4];
            #pragma unroll
            for (int i = 0; i < 4; i++) a[i] = sQ[(ty * 4 + i) * 65 + d];
            #pragma unroll
            for (int j = 0; j < 4; j++) k[j] = sK[(tx * 4 + j) * 65 + d];
            #pragma unroll
            for (int i = 0; i < 4; i++)
                #pragma unroll
                for (int j = 0; j < 4; j++)
                    s[i][j] = fmaf(a[i], k[j], s[i][j]);
        }
        #pragma unroll
        for (int i = 0; i < 4; i++)
            #pragma unroll
            for (int j = 0; j < 4; j++)
                sS[(ty * 4 + i) * 65 + tx * 4 + j] = s[i][j] * scale;
        __syncthreads();

        // Online softmax: thread r handles row r (r < 64)
        if (t < 64) {
            float mo = rm[t];
            float mx = mo;
            #pragma unroll 8
            for (int j = 0; j < 64; j++) mx = fmaxf(mx, sS[t * 65 + j]);
            float sum = 0.f;
            #pragma unroll 8
            for (int j = 0; j < 64; j++) {
                float e = expf(sS[t * 65 + j] - mx);
                sS[t * 65 + j] = e;
                sum += e;
            }
            float f = expf(mo - mx);
            rf[t] = f;
            rl[t] = rl[t] * f + sum;
            rm[t] = mx;
        }
        __syncthreads();

        // Rescale O, then O += P V
        #pragma unroll
        for (int i = 0; i < 4; i++) {
            float f = rf[ty * 4 + i];
            #pragma unroll
            for (int j = 0; j < 4; j++) O[i][j] *= f;
        }
        #pragma unroll 8
        for (int kk = 0; kk < 64; kk++) {
            float p[4], v[4];
            #pragma unroll
            for (int i = 0; i < 4; i++) p[i] = sS[(ty * 4 + i) * 65 + kk];
            #pragma unroll
            for (int j = 0; j < 4; j++) v[j] = sV[kk * 65 + tx * 4 + j];
            #pragma unroll
            for (int i = 0; i < 4; i++)
                #pragma unroll
                for (int j = 0; j < 4; j++)
                    O[i][j] = fmaf(p[i], v[j], O[i][j]);
        }
        __syncthreads();
    }

    // Epilogue: normalize, exact GELU, stage in smem, coalesced writeback
    #pragma unroll
    for (int i = 0; i < 4; i++) {
        float inv = 1.f / rl[ty * 4 + i];
        #pragma unroll
        for (int j = 0; j < 4; j++) {
            float v = O[i][j] * inv;
            float g = 0.5f * v * (1.f + erff(v * 0.70710678118654752f));
            sS[(ty * 4 + i) * 65 + tx * 4 + j] = g;
        }
    }
    __syncthreads();
    for (int idx = t; idx < 4096; idx += 256) {
        int d = idx >> 6, qi = idx & 63;
        ob[(size_t)d * NPIX + q0 + qi] = sS[qi * 65 + d];
    }
}

// ---------------------------------------------------------------------------
extern "C" void kernel_launch(void* const* d_in, const int* in_sizes, int n_in,
                              void* d_out, int out_size)
{
    const float* x    = (const float*)d_in[0];  // [8,256,32,32]
    const float* Wq   = (const float*)d_in[1];  // [512,256,1,1]
    const float* Wkv  = (const float*)d_in[2];  // [1024,256,3,3]
    const float* Wout = (const float*)d_in[3];  // [256,512,1,1]
    const float* bout = (const float*)d_in[4];  // [256]
    float* out = (float*)d_out;                 // [8,256,32,32]

    float *qp, *kvp, *aop;
    cudaGetSymbolAddress((void**)&qp,  g_Q);
    cudaGetSymbolAddress((void**)&kvp, g_KV);
    cudaGetSymbolAddress((void**)&aop, g_AO);

    dim3 blk(256);

    // 1) Q = Wq * x        (M=512, N=1024, K=256, per batch)
    gemm_1x1<0><<<dim3(NPIX / 64, INNER / 64, BATCH), blk>>>(
        Wq, x, qp, nullptr, INNER, NPIX, C_IN);

    // 2) KV = conv3x3(x)   (M=1024, N=1024, K=2304, per batch)
    conv3x3_kv<<<dim3(NPIX / 64, MKV / 64, BATCH), blk>>>(Wkv, x);

    // 3) Flash attention + GELU fused
    int smem = FA_SMEM_FLOATS * (int)sizeof(float);  // 67328 B
    cudaFuncSetAttribute(flash_attn,
                         cudaFuncAttributeMaxDynamicSharedMemorySize, smem);
    flash_attn<<<dim3(NPIX / 64, BATCH * HEADS), blk, smem>>>(qp, kvp, aop);

    // 4) out = Wout * gelu_attn + bout   (M=256, N=1024, K=512, per batch)
    gemm_1x1<1><<<dim3(NPIX / 64, 256 / 64, BATCH), blk>>>(
        Wout, aop, out, bout, 256, NPIX, INNER);
}

// round 8
// speedup vs baseline: 1.0008x; 1.0008x over previous
#include <cuda_runtime.h>
#include <math.h>

// Problem constants (fixed shapes from reference)
#define BATCH  8
#define C_IN   256
#define NPIX   1024   // 32*32
#define INNER  512    // heads*dim_head
#define HEADS  8
#define DH     64
#define KCONV  2304   // 256*9
#define MKV    1024   // 2*INNER

// Scratch (static device globals — no allocation allowed)
__device__ float g_Q [(size_t)BATCH * INNER * NPIX];   // [b][h*64+d][p]
__device__ float g_KV[(size_t)BATCH * MKV   * NPIX];   // [b][co][p], co<512: K, co>=512: V
__device__ float g_AO[(size_t)BATCH * INNER * NPIX];   // gelu(attention out), [b][h*64+d][p]

// ---------------------------------------------------------------------------
// Generic tiled GEMM for 1x1 convs:
//   C[z][m][n] = sum_k A[m][k] * B[z][k][n]  (+ bias[m])
// Tile 64x64, BK=16, 256 threads, 4x4 per thread.
// ---------------------------------------------------------------------------
template<int BIAS>
__global__ __launch_bounds__(256)
void gemm_1x1(const float* __restrict__ A, const float* __restrict__ Bm,
              float* __restrict__ Cm, const float* __restrict__ bias,
              int M, int N, int K)
{
    __shared__ float sA[16][65];
    __shared__ float sB[16][65];
    const int t  = threadIdx.x;
    const int tx = t & 15, ty = t >> 4;
    const int n0 = blockIdx.x * 64, m0 = blockIdx.y * 64;
    const float* Bp = Bm + (size_t)blockIdx.z * K * N;
    float*       Cp = Cm + (size_t)blockIdx.z * M * N;

    float acc[4][4] = {};
    for (int k0 = 0; k0 < K; k0 += 16) {
        #pragma unroll
        for (int r = 0; r < 4; r++) {
            int idx = t + r * 256;
            { int kk = idx & 15, m = idx >> 4;
              sA[kk][m] = A[(size_t)(m0 + m) * K + k0 + kk]; }
            { int nn = idx & 63, kk = idx >> 6;
              sB[kk][nn] = Bp[(size_t)(k0 + kk) * N + n0 + nn]; }
        }
        __syncthreads();
        #pragma unroll
        for (int kk = 0; kk < 16; kk++) {
            float a[4], b[4];
            #pragma unroll
            for (int i = 0; i < 4; i++) a[i] = sA[kk][ty * 4 + i];
            #pragma unroll
            for (int j = 0; j < 4; j++) b[j] = sB[kk][tx * 4 + j];
            #pragma unroll
            for (int i = 0; i < 4; i++)
                #pragma unroll
                for (int j = 0; j < 4; j++)
                    acc[i][j] = fmaf(a[i], b[j], acc[i][j]);
        }
        __syncthreads();
    }
    #pragma unroll
    for (int i = 0; i < 4; i++) {
        int m = m0 + ty * 4 + i;
        float bv = BIAS ? bias[m] : 0.f;
        #pragma unroll
        for (int j = 0; j < 4; j++)
            Cp[(size_t)m * N + n0 + tx * 4 + j] = acc[i][j] + bv;
    }
}

// ---------------------------------------------------------------------------
// 3x3 conv (pad=1) as implicit GEMM:
//   KV[b][co][p] = sum_{k=ci*9+tap} W[co][k] * X[b][ci][shift_tap(p)]
// M=1024, N=1024, K=2304. Same 64x64 tile scheme; B-tile load does the
// im2col gather with boundary predication.
// ---------------------------------------------------------------------------
__global__ __launch_bounds__(256)
void conv3x3_kv(const float* __restrict__ W, const float* __restrict__ X)
{
    __shared__ float sA[16][65];
    __shared__ float sB[16][65];
    const int t  = threadIdx.x;
    const int tx = t & 15, ty = t >> 4;
    const int n0 = blockIdx.x * 64, m0 = blockIdx.y * 64;
    const float* Xp = X    + (size_t)blockIdx.z * C_IN * NPIX;
    float*       Cp = g_KV + (size_t)blockIdx.z * MKV  * NPIX;

    float acc[4][4] = {};
    for (int k0 = 0; k0 < KCONV; k0 += 16) {
        #pragma unroll
        for (int r = 0; r < 4; r++) {
            int idx = t + r * 256;
            { int kk = idx & 15, m = idx >> 4;
              sA[kk][m] = W[(size_t)(m0 + m) * KCONV + k0 + kk]; }
            { int nn = idx & 63, kk = idx >> 6;
              int kg  = k0 + kk;
              int ci  = kg / 9;
              int tap = kg - ci * 9;
              int dy  = tap / 3 - 1;
              int dx  = tap - (tap / 3) * 3 - 1;
              int n   = n0 + nn;
              int y   = (n >> 5) + dy;
              int x   = (n & 31) + dx;
              float v = 0.f;
              if ((unsigned)y < 32u && (unsigned)x < 32u)
                  v = Xp[(size_t)ci * NPIX + (y << 5) + x];
              sB[kk][nn] = v; }
        }
        __syncthreads();
        #pragma unroll
        for (int kk = 0; kk < 16; kk++) {
            float a[4], b[4];
            #pragma unroll
            for (int i = 0; i < 4; i++) a[i] = sA[kk][ty * 4 + i];
            #pragma unroll
            for (int j = 0; j < 4; j++) b[j] = sB[kk][tx * 4 + j];
            #pragma unroll
            for (int i = 0; i < 4; i++)
                #pragma unroll
                for (int j = 0; j < 4; j++)
                    acc[i][j] = fmaf(a[i], b[j], acc[i][j]);
        }
        __syncthreads();
    }
    #pragma unroll
    for (int i = 0; i < 4; i++) {
        int m = m0 + ty * 4 + i;
        #pragma unroll
        for (int j = 0; j < 4; j++)
            Cp[(size_t)m * NPIX + n0 + tx * 4 + j] = acc[i][j];
    }
}

// ---------------------------------------------------------------------------
// Flash attention (fp32, exact): one CTA per (b*h, 64-query tile).
// n=1024 keys, d=64. Online softmax, O accumulator in registers (4x4/thread).
// GELU (exact, erf) fused into epilogue; coalesced writeback via smem stage.
// ---------------------------------------------------------------------------
#define FA_SMEM_FLOATS (4 * 64 * 65 + 3 * 64)

__global__ __launch_bounds__(256)
void flash_attn(const float* __restrict__ Q, const float* __restrict__ KV,
                float* __restrict__ AO)
{
    extern __shared__ float sm[];
    float* sQ = sm;               // [64][65]
    float* sK = sQ + 64 * 65;     // [64][65]
    float* sV = sK + 64 * 65;     // [64][65]
    float* sS = sV + 64 * 65;     // [64][65]
    float* rm = sS + 64 * 65;     // [64] running max
    float* rl = rm + 64;          // [64] running denom
    float* rf = rl + 64;          // [64] rescale factor

    const int t  = threadIdx.x;
    const int tx = t & 15, ty = t >> 4;
    const int q0 = blockIdx.x * 64;
    const int bh = blockIdx.y;
    const int b  = bh >> 3, h = bh & 7;

    const float* qb = Q  + ((size_t)b * INNER + h * DH) * NPIX;
    const float* kb = KV + ((size_t)b * MKV   + h * DH) * NPIX;
    const float* vb = KV + ((size_t)b * MKV + INNER + h * DH) * NPIX;
    float*       ob = AO + ((size_t)b * INNER + h * DH) * NPIX;

    // Load Q tile: sQ[qi][d]  (coalesced over p, conflict-free stride-65 store)
    for (int idx = t; idx < 4096; idx += 256) {
        int d = idx >> 6, qi = idx & 63;
        sQ[qi * 65 + d] = qb[(size_t)d * NPIX + q0 + qi];
    }
    if (t < 64) { rm[t] = -1e30f; rl[t] = 0.f; }

    float O[4][4] = {};
    const float scale = 0.125f;  // 64^-0.5

    for (int k0 = 0; k0 < NPIX; k0 += 64) {
        for (int idx = t; idx < 4096; idx += 256) {
            int d = idx >> 6, ki = idx & 63;
            sK[ki * 65 + d] = kb[(size_t)d * NPIX + k0 + ki];
            sV[ki * 65 + d] = vb[(size_t)d * NPIX + k0 + ki];
        }
        __syncthreads();

        // S = scale * Q K^T  (64x64 tile, regs)
        float s[4][4] = {};
        #pragma unroll 8
        for (int d = 0; d < 64; d++) {
            float a[4], k[4];
            #pragma unroll
            for (int i = 0; i < 4; i++) a[i] = sQ[(ty * 4 + i) * 65 + d];
            #pragma unroll
            for (int j = 0; j < 4; j++) k[j] = sK[(tx * 4 + j) * 65 + d];
            #pragma unroll
            for (int i = 0; i < 4; i++)
                #pragma unroll
                for (int j = 0; j < 4; j++)
                    s[i][j] = fmaf(a[i], k[j], s[i][j]);
        }
        #pragma unroll
        for (int i = 0; i < 4; i++)
            #pragma unroll
            for (int j = 0; j < 4; j++)
                sS[(ty * 4 + i) * 65 + tx * 4 + j] = s[i][j] * scale;
        __syncthreads();

        // Online softmax: thread r handles row r (r < 64)
        if (t < 64) {
            float mo = rm[t];
            float mx = mo;
            #pragma unroll 8
            for (int j = 0; j < 64; j++) mx = fmaxf(mx, sS[t * 65 + j]);
            float sum = 0.f;
            #pragma unroll 8
            for (int j = 0; j < 64; j++) {
                float e = expf(sS[t * 65 + j] - mx);
                sS[t * 65 + j] = e;
                sum += e;
            }
            float f = expf(mo - mx);
            rf[t] = f;
            rl[t] = rl[t] * f + sum;
            rm[t] = mx;
        }
        __syncthreads();

        // Rescale O, then O += P V
        #pragma unroll
        for (int i = 0; i < 4; i++) {
            float f = rf[ty * 4 + i];
            #pragma unroll
            for (int j = 0; j < 4; j++) O[i][j] *= f;
        }
        #pragma unroll 8
        for (int kk = 0; kk < 64; kk++) {
            float p[4], v[4];
            #pragma unroll
            for (int i = 0; i < 4; i++) p[i] = sS[(ty * 4 + i) * 65 + kk];
            #pragma unroll
            for (int j = 0; j < 4; j++) v[j] = sV[kk * 65 + tx * 4 + j];
            #pragma unroll
            for (int i = 0; i < 4; i++)
                #pragma unroll
                for (int j = 0; j < 4; j++)
                    O[i][j] = fmaf(p[i], v[j], O[i][j]);
        }
        __syncthreads();
    }

    // Epilogue: normalize, exact GELU, stage in smem, coalesced writeback
    #pragma unroll
    for (int i = 0; i < 4; i++) {
        float inv = 1.f / rl[ty * 4 + i];
        #pragma unroll
        for (int j = 0; j < 4; j++) {
            float v = O[i][j] * inv;
            float g = 0.5f * v * (1.f + erff(v * 0.70710678118654752f));
            sS[(ty * 4 + i) * 65 + tx * 4 + j] = g;
        }
    }
    __syncthreads();
    for (int idx = t; idx < 4096; idx += 256) {
        int d = idx >> 6, qi = idx & 63;
        ob[(size_t)d * NPIX + q0 + qi] = sS[qi * 65 + d];
    }
}

// ---------------------------------------------------------------------------
extern "C" void kernel_launch(void* const* d_in, const int* in_sizes, int n_in,
                              void* d_out, int out_size)
{
    const float* x    = (const float*)d_in[0];  // [8,256,32,32]
    const float* Wq   = (const float*)d_in[1];  // [512,256,1,1]
    const float* Wkv  = (const float*)d_in[2];  // [1024,256,3,3]
    const float* Wout = (const float*)d_in[3];  // [256,512,1,1]
    const float* bout = (const float*)d_in[4];  // [256]
    float* out = (float*)d_out;                 // [8,256,32,32]

    float *qp, *kvp, *aop;
    cudaGetSymbolAddress((void**)&qp,  g_Q);
    cudaGetSymbolAddress((void**)&kvp, g_KV);
    cudaGetSymbolAddress((void**)&aop, g_AO);

    dim3 blk(256);

    // 1) Q = Wq * x        (M=512, N=1024, K=256, per batch)
    gemm_1x1<0><<<dim3(NPIX / 64, INNER / 64, BATCH), blk>>>(
        Wq, x, qp, nullptr, INNER, NPIX, C_IN);

    // 2) KV = conv3x3(x)   (M=1024, N=1024, K=2304, per batch)
    conv3x3_kv<<<dim3(NPIX / 64, MKV / 64, BATCH), blk>>>(Wkv, x);

    // 3) Flash attention + GELU fused
    int smem = FA_SMEM_FLOATS * (int)sizeof(float);  // 67328 B
    cudaFuncSetAttribute(flash_attn,
                         cudaFuncAttributeMaxDynamicSharedMemorySize, smem);
    flash_attn<<<dim3(NPIX / 64, BATCH * HEADS), blk, smem>>>(qp, kvp, aop);

    // 4) out = Wout * gelu_attn + bout   (M=256, N=1024, K=512, per batch)
    gemm_1x1<1><<<dim3(NPIX / 64, 256 / 64, BATCH), blk>>>(
        Wout, aop, out, bout, 256, NPIX, INNER);
}

// round 10
// speedup vs baseline: 1.5769x; 1.5756x over previous
#include <cuda_runtime.h>
#include <cuda_bf16.h>
#include <cstdint>
#include <math.h>

// Problem constants (fixed shapes from reference)
#define BATCH  8
#define C_IN   256
#define NPIX   1024   // 32*32
#define INNER  512    // heads*dim_head
#define HEADS  8
#define DH     64
#define KCONV  2304   // 256*9
#define MKV    1024   // 2*INNER

// Scratch (static device globals — no allocation allowed)
__device__ float g_Q [(size_t)BATCH * INNER * NPIX];   // [b][h*64+d][p]
__device__ float g_KV[(size_t)BATCH * MKV   * NPIX];   // [b][co][p], co<512: K, co>=512: V
__device__ float g_AO[(size_t)BATCH * INNER * NPIX];   // gelu(attention out), [b][h*64+d][p]

// ===========================================================================
// mma.sync helpers (HMMA — supported on plain sm_103; tcgen05 is NOT,
// the harness PTX target is sm_103 without the 'a' suffix)
// ===========================================================================
__device__ __forceinline__ uint32_t smem_u32(const void* p) {
    uint32_t a;
    asm("{ .reg .u64 t; cvta.to.shared.u64 t, %1; cvt.u32.u64 %0, t; }"
        : "=r"(a) : "l"(p));
    return a;
}
__device__ __forceinline__ void ldmx4(uint32_t* r, uint32_t addr) {
    asm volatile("ldmatrix.sync.aligned.m8n8.x4.shared.b16 {%0,%1,%2,%3}, [%4];"
        : "=r"(r[0]), "=r"(r[1]), "=r"(r[2]), "=r"(r[3]) : "r"(addr));
}
__device__ __forceinline__ void mma_bf16(float* c, const uint32_t* a,
                                         uint32_t b0, uint32_t b1) {
    asm volatile(
        "mma.sync.aligned.m16n8k16.row.col.f32.bf16.bf16.f32 "
        "{%0,%1,%2,%3}, {%4,%5,%6,%7}, {%8,%9}, {%0,%1,%2,%3};"
        : "+f"(c[0]), "+f"(c[1]), "+f"(c[2]), "+f"(c[3])
        : "r"(a[0]), "r"(a[1]), "r"(a[2]), "r"(a[3]), "r"(b0), "r"(b1));
}

// ===========================================================================
// 3x3 conv (pad=1) as implicit GEMM on mma.sync, bf16x3 split for fp32 accuracy:
//   KV[b][co][p] = sum_k W[co][k] * im2col(X)[k][p]
// CTA: 128 co x 64 pix. K=2304 in 36 panels of 64. 8 warps: 4(M) x 2(N),
// warp tile 32x32 (2 m-tiles x 4 n-tiles of m16n8k16).
// smem: Ahi/Alo [128][72] bf16, Bhi/Blo [64][72] bf16 = 55296 B.
// ===========================================================================
#define ASTR 72
#define CONV_SMEM 55296

__global__ __launch_bounds__(256)
void conv3x3_mma(const float* __restrict__ W, const float* __restrict__ X)
{
    extern __shared__ char smem[];
    __nv_bfloat16* sAhi = (__nv_bfloat16*)smem;                 // 128*72
    __nv_bfloat16* sAlo = sAhi + 128 * ASTR;
    __nv_bfloat16* sBhi = sAlo + 128 * ASTR;                    // 64*72
    __nv_bfloat16* sBlo = sBhi + 64 * ASTR;
    const uint32_t uAhi = smem_u32(sAhi), uAlo = smem_u32(sAlo);
    const uint32_t uBhi = smem_u32(sBhi), uBlo = smem_u32(sBlo);

    const int t    = threadIdx.x;
    const int warp = t >> 5, lane = t & 31;
    const int wm   = warp & 3;        // warp row (M)
    const int wn   = warp >> 2;       // warp col (N)
    const int n0   = blockIdx.x * 64;
    const int m0   = blockIdx.y * 128;
    const float* Xp = X    + (size_t)blockIdx.z * C_IN * NPIX;
    float*       Cp = g_KV + (size_t)blockIdx.z * MKV  * NPIX;

    // ldmatrix source addresses (per k-step we add the k byte offset)
    const int arow  = (lane & 15);
    const int acolb = (lane >> 4) * 16;                   // byte offset within row
    const int brow  = (lane & 7) + ((lane >> 4) << 3);
    const int bcolb = ((lane >> 3) & 1) * 16;

    float acc[2][4][4] = {};

    for (int p = 0; p < 36; p++) {
        const int k0 = p * 64;

        // --- A panel: weights 128 x 64, hi/lo split ---
        #pragma unroll
        for (int r = 0; r < 16; r++) {
            int i  = t + r * 256;
            int kp = i & 31, m = i >> 5;
            float2 w2 = *(const float2*)(W + (size_t)(m0 + m) * KCONV + k0 + 2 * kp);
            __nv_bfloat162 hi, lo;
            hi.x = __float2bfloat16(w2.x);
            hi.y = __float2bfloat16(w2.y);
            lo.x = __float2bfloat16(w2.x - __bfloat162float(hi.x));
            lo.y = __float2bfloat16(w2.y - __bfloat162float(hi.y));
            *(__nv_bfloat162*)(sAhi + m * ASTR + 2 * kp) = hi;
            *(__nv_bfloat162*)(sAlo + m * ASTR + 2 * kp) = lo;
        }
        // --- B panel: im2col gather 64 pix x 64 k, hi/lo split ---
        #pragma unroll
        for (int r = 0; r < 8; r++) {
            int i  = t + r * 256;
            int kp = i & 31, nn = i >> 5;
            int n = n0 + nn, py = n >> 5, px = n & 31;
            float v0, v1;
            {
                int kg = k0 + 2 * kp;
                int ci = kg / 9, tap = kg - ci * 9;
                int y = py + tap / 3 - 1, x = px + tap - (tap / 3) * 3 - 1;
                v0 = ((unsigned)y < 32u && (unsigned)x < 32u)
                     ? Xp[(size_t)ci * NPIX + (y << 5) + x] : 0.f;
            }
            {
                int kg = k0 + 2 * kp + 1;
                int ci = kg / 9, tap = kg - ci * 9;
                int y = py + tap / 3 - 1, x = px + tap - (tap / 3) * 3 - 1;
                v1 = ((unsigned)y < 32u && (unsigned)x < 32u)
                     ? Xp[(size_t)ci * NPIX + (y << 5) + x] : 0.f;
            }
            __nv_bfloat162 hi, lo;
            hi.x = __float2bfloat16(v0);
            hi.y = __float2bfloat16(v1);
            lo.x = __float2bfloat16(v0 - __bfloat162float(hi.x));
            lo.y = __float2bfloat16(v1 - __bfloat162float(hi.y));
            *(__nv_bfloat162*)(sBhi + nn * ASTR + 2 * kp) = hi;
            *(__nv_bfloat162*)(sBlo + nn * ASTR + 2 * kp) = lo;
        }
        __syncthreads();

        #pragma unroll
        for (int ks = 0; ks < 4; ks++) {
            const int kb = ks * 32;  // k-step byte offset (16 bf16)
            uint32_t ah[2][4], al[2][4], bh[2][4], bl[2][4];
            #pragma unroll
            for (int mt = 0; mt < 2; mt++) {
                uint32_t off = (uint32_t)((wm * 32 + mt * 16 + arow) * ASTR) * 2
                             + kb + acolb;
                ldmx4(ah[mt], uAhi + off);
                ldmx4(al[mt], uAlo + off);
            }
            #pragma unroll
            for (int nt2 = 0; nt2 < 2; nt2++) {
                uint32_t off = (uint32_t)((wn * 32 + nt2 * 16 + brow) * ASTR) * 2
                             + kb + bcolb;
                ldmx4(bh[nt2], uBhi + off);
                ldmx4(bl[nt2], uBlo + off);
            }
            #pragma unroll
            for (int mt = 0; mt < 2; mt++)
                #pragma unroll
                for (int nt = 0; nt < 4; nt++) {
                    uint32_t b0h = bh[nt >> 1][(nt & 1) * 2];
                    uint32_t b1h = bh[nt >> 1][(nt & 1) * 2 + 1];
                    uint32_t b0l = bl[nt >> 1][(nt & 1) * 2];
                    uint32_t b1l = bl[nt >> 1][(nt & 1) * 2 + 1];
                    mma_bf16(acc[mt][nt], ah[mt], b0h, b1h);   // hi*hi
                    mma_bf16(acc[mt][nt], ah[mt], b0l, b1l);   // hi*lo
                    mma_bf16(acc[mt][nt], al[mt], b0h, b1h);   // lo*hi
                }
        }
        __syncthreads();
    }

    // Epilogue: stage fp32 result in smem (stride 66), coalesced writeback
    float* sO = (float*)smem;   // [128][66] = 33792 B (panels no longer needed)
    #pragma unroll
    for (int mt = 0; mt < 2; mt++)
        #pragma unroll
        for (int nt = 0; nt < 4; nt++) {
            int row = wm * 32 + mt * 16 + (lane >> 2);
            int col = wn * 32 + nt * 8 + (lane & 3) * 2;
            *(float2*)(sO + row * 66 + col) =
                make_float2(acc[mt][nt][0], acc[mt][nt][1]);
            *(float2*)(sO + (row + 8) * 66 + col) =
                make_float2(acc[mt][nt][2], acc[mt][nt][3]);
        }
    __syncthreads();
    for (int i = t; i < 8192; i += 256) {
        int m = i >> 6, c = i & 63;
        Cp[(size_t)(m0 + m) * NPIX + n0 + c] = sO[m * 66 + c];
    }
}

// ---------------------------------------------------------------------------
// Generic tiled GEMM for 1x1 convs (unchanged):
//   C[z][m][n] = sum_k A[m][k] * B[z][k][n]  (+ bias[m])
// ---------------------------------------------------------------------------
template<int BIAS>
__global__ __launch_bounds__(256)
void gemm_1x1(const float* __restrict__ A, const float* __restrict__ Bm,
              float* __restrict__ Cm, const float* __restrict__ bias,
              int M, int N, int K)
{
    __shared__ float sA[16][65];
    __shared__ float sB[16][65];
    const int t  = threadIdx.x;
    const int tx = t & 15, ty = t >> 4;
    const int n0 = blockIdx.x * 64, m0 = blockIdx.y * 64;
    const float* Bp = Bm + (size_t)blockIdx.z * K * N;
    float*       Cp = Cm + (size_t)blockIdx.z * M * N;

    float acc[4][4] = {};
    for (int k0 = 0; k0 < K; k0 += 16) {
        #pragma unroll
        for (int r = 0; r < 4; r++) {
            int idx = t + r * 256;
            { int kk = idx & 15, m = idx >> 4;
              sA[kk][m] = A[(size_t)(m0 + m) * K + k0 + kk]; }
            { int nn = idx & 63, kk = idx >> 6;
              sB[kk][nn] = Bp[(size_t)(k0 + kk) * N + n0 + nn]; }
        }
        __syncthreads();
        #pragma unroll
        for (int kk = 0; kk < 16; kk++) {
            float a[4], b[4];
            #pragma unroll
            for (int i = 0; i < 4; i++) a[i] = sA[kk][ty * 4 + i];
            #pragma unroll
            for (int j = 0; j < 4; j++) b[j] = sB[kk][tx * 4 + j];
            #pragma unroll
            for (int i = 0; i < 4; i++)
                #pragma unroll
                for (int j = 0; j < 4; j++)
                    acc[i][j] = fmaf(a[i], b[j], acc[i][j]);
        }
        __syncthreads();
    }
    #pragma unroll
    for (int i = 0; i < 4; i++) {
        int m = m0 + ty * 4 + i;
        float bv = BIAS ? bias[m] : 0.f;
        #pragma unroll
        for (int j = 0; j < 4; j++)
            Cp[(size_t)m * N + n0 + tx * 4 + j] = acc[i][j] + bv;
    }
}

// ---------------------------------------------------------------------------
// Flash attention (fp32, exact, unchanged): one CTA per (b*h, 64-query tile).
// ---------------------------------------------------------------------------
#define FA_SMEM_FLOATS (4 * 64 * 65 + 3 * 64)

__global__ __launch_bounds__(256)
void flash_attn(const float* __restrict__ Q, const float* __restrict__ KV,
                float* __restrict__ AO)
{
    extern __shared__ float sm[];
    float* sQ = sm;               // [64][65]
    float* sK = sQ + 64 * 65;     // [64][65]
    float* sV = sK + 64 * 65;     // [64][65]
    float* sS = sV + 64 * 65;     // [64][65]
    float* rm = sS + 64 * 65;     // [64] running max
    float* rl = rm + 64;          // [64] running denom
    float* rf = rl + 64;          // [64] rescale factor

    const int t  = threadIdx.x;
    const int tx = t & 15, ty = t >> 4;
    const int q0 = blockIdx.x * 64;
    const int bh = blockIdx.y;
    const int b  = bh >> 3, h = bh & 7;

    const float* qb = Q  + ((size_t)b * INNER + h * DH) * NPIX;
    const float* kb = KV + ((size_t)b * MKV   + h * DH) * NPIX;
    const float* vb = KV + ((size_t)b * MKV + INNER + h * DH) * NPIX;
    float*       ob = AO + ((size_t)b * INNER + h * DH) * NPIX;

    for (int idx = t; idx < 4096; idx += 256) {
        int d = idx >> 6, qi = idx & 63;
        sQ[qi * 65 + d] = qb[(size_t)d * NPIX + q0 + qi];
    }
    if (t < 64) { rm[t] = -1e30f; rl[t] = 0.f; }

    float O[4][4] = {};
    const float scale = 0.125f;  // 64^-0.5

    for (int k0 = 0; k0 < NPIX; k0 += 64) {
        for (int idx = t; idx < 4096; idx += 256) {
            int d = idx >> 6, ki = idx & 63;
            sK[ki * 65 + d] = kb[(size_t)d * NPIX + k0 + ki];
            sV[ki * 65 + d] = vb[(size_t)d * NPIX + k0 + ki];
        }
        __syncthreads();

        float s[4][4] = {};
        #pragma unroll 8
        for (int d = 0; d < 64; d++) {
            float a[4], k[4];
            #pragma unroll
            for (int i = 0; i < 4; i++) a[i] = sQ[(ty * 4 + i) * 65 + d];
            #pragma unroll
            for (int j = 0; j < 4; j++) k[j] = sK[(tx * 4 + j) * 65 + d];
            #pragma unroll
            for (int i = 0; i < 4; i++)
                #pragma unroll
                for (int j = 0; j < 4; j++)
                    s[i][j] = fmaf(a[i], k[j], s[i][j]);
        }
        #pragma unroll
        for (int i = 0; i < 4; i++)
            #pragma unroll
            for (int j = 0; j < 4; j++)
                sS[(ty * 4 + i) * 65 + tx * 4 + j] = s[i][j] * scale;
        __syncthreads();

        if (t < 64) {
            float mo = rm[t];
            float mx = mo;
            #pragma unroll 8
            for (int j = 0; j < 64; j++) mx = fmaxf(mx, sS[t * 65 + j]);
            float sum = 0.f;
            #pragma unroll 8
            for (int j = 0; j < 64; j++) {
                float e = expf(sS[t * 65 + j] - mx);
                sS[t * 65 + j] = e;
                sum += e;
            }
            float f = expf(mo - mx);
            rf[t] = f;
            rl[t] = rl[t] * f + sum;
            rm[t] = mx;
        }
        __syncthreads();

        #pragma unroll
        for (int i = 0; i < 4; i++) {
            float f = rf[ty * 4 + i];
            #pragma unroll
            for (int j = 0; j < 4; j++) O[i][j] *= f;
        }
        #pragma unroll 8
        for (int kk = 0; kk < 64; kk++) {
            float p[4], v[4];
            #pragma unroll
            for (int i = 0; i < 4; i++) p[i] = sS[(ty * 4 + i) * 65 + kk];
            #pragma unroll
            for (int j = 0; j < 4; j++) v[j] = sV[kk * 65 + tx * 4 + j];
            #pragma unroll
            for (int i = 0; i < 4; i++)
                #pragma unroll
                for (int j = 0; j < 4; j++)
                    O[i][j] = fmaf(p[i], v[j], O[i][j]);
        }
        __syncthreads();
    }

    #pragma unroll
    for (int i = 0; i < 4; i++) {
        float inv = 1.f / rl[ty * 4 + i];
        #pragma unroll
        for (int j = 0; j < 4; j++) {
            float v = O[i][j] * inv;
            float g = 0.5f * v * (1.f + erff(v * 0.70710678118654752f));
            sS[(ty * 4 + i) * 65 + tx * 4 + j] = g;
        }
    }
    __syncthreads();
    for (int idx = t; idx < 4096; idx += 256) {
        int d = idx >> 6, qi = idx & 63;
        ob[(size_t)d * NPIX + q0 + qi] = sS[qi * 65 + d];
    }
}

// ---------------------------------------------------------------------------
extern "C" void kernel_launch(void* const* d_in, const int* in_sizes, int n_in,
                              void* d_out, int out_size)
{
    const float* x    = (const float*)d_in[0];  // [8,256,32,32]
    const float* Wq   = (const float*)d_in[1];  // [512,256,1,1]
    const float* Wkv  = (const float*)d_in[2];  // [1024,256,3,3]
    const float* Wout = (const float*)d_in[3];  // [256,512,1,1]
    const float* bout = (const float*)d_in[4];  // [256]
    float* out = (float*)d_out;                 // [8,256,32,32]

    float *qp, *kvp, *aop;
    cudaGetSymbolAddress((void**)&qp,  g_Q);
    cudaGetSymbolAddress((void**)&kvp, g_KV);
    cudaGetSymbolAddress((void**)&aop, g_AO);

    dim3 blk(256);

    // 1) Q = Wq * x        (M=512, N=1024, K=256, per batch)
    gemm_1x1<0><<<dim3(NPIX / 64, INNER / 64, BATCH), blk>>>(
        Wq, x, qp, nullptr, INNER, NPIX, C_IN);

    // 2) KV = conv3x3(x) on mma.sync bf16x3  (M=1024, N=1024, K=2304, per batch)
    cudaFuncSetAttribute(conv3x3_mma,
                         cudaFuncAttributeMaxDynamicSharedMemorySize, CONV_SMEM);
    conv3x3_mma<<<dim3(NPIX / 64, MKV / 128, BATCH), blk, CONV_SMEM>>>(Wkv, x);

    // 3) Flash attention + GELU fused
    int smem = FA_SMEM_FLOATS * (int)sizeof(float);  // 67328 B
    cudaFuncSetAttribute(flash_attn,
                         cudaFuncAttributeMaxDynamicSharedMemorySize, smem);
    flash_attn<<<dim3(NPIX / 64, BATCH * HEADS), blk, smem>>>(qp, kvp, aop);

    // 4) out = Wout * gelu_attn + bout   (M=256, N=1024, K=512, per batch)
    gemm_1x1<1><<<dim3(NPIX / 64, 256 / 64, BATCH), blk>>>(
        Wout, aop, out, bout, 256, NPIX, INNER);
}

// round 11
// speedup vs baseline: 1.6775x; 1.0638x over previous
#include <cuda_runtime.h>
#include <cuda_bf16.h>
#include <cstdint>
#include <math.h>

// Problem constants (fixed shapes from reference)
#define BATCH  8
#define C_IN   256
#define NPIX   1024   // 32*32
#define INNER  512    // heads*dim_head
#define HEADS  8
#define DH     64
#define KCONV  2304   // 256*9
#define MKV    1024   // 2*INNER

// Scratch (static device globals — no allocation allowed)
__device__ float g_Q [(size_t)BATCH * INNER * NPIX];   // [b][h*64+d][p]
__device__ float g_KV[(size_t)BATCH * MKV   * NPIX];   // [b][co][p], co<512: K, co>=512: V
__device__ float g_AO[(size_t)BATCH * INNER * NPIX];   // gelu(attention out), [b][h*64+d][p]

// ===========================================================================
// mma.sync helpers (HMMA — supported on plain sm_103; tcgen05 is NOT:
// the harness PTX target is sm_103 without the 'a' suffix)
// ===========================================================================
__device__ __forceinline__ uint32_t smem_u32(const void* p) {
    uint32_t a;
    asm("{ .reg .u64 t; cvta.to.shared.u64 t, %1; cvt.u32.u64 %0, t; }"
        : "=r"(a) : "l"(p));
    return a;
}
__device__ __forceinline__ void ldmx4(uint32_t* r, uint32_t addr) {
    asm volatile("ldmatrix.sync.aligned.m8n8.x4.shared.b16 {%0,%1,%2,%3}, [%4];"
        : "=r"(r[0]), "=r"(r[1]), "=r"(r[2]), "=r"(r[3]) : "r"(addr));
}
__device__ __forceinline__ void mma_bf16(float* c, const uint32_t* a,
                                         uint32_t b0, uint32_t b1) {
    asm volatile(
        "mma.sync.aligned.m16n8k16.row.col.f32.bf16.bf16.f32 "
        "{%0,%1,%2,%3}, {%4,%5,%6,%7}, {%8,%9}, {%0,%1,%2,%3};"
        : "+f"(c[0]), "+f"(c[1]), "+f"(c[2]), "+f"(c[3])
        : "r"(a[0]), "r"(a[1]), "r"(a[2]), "r"(a[3]), "r"(b0), "r"(b1));
}
__device__ __forceinline__ void split2(float v, __nv_bfloat16& h, __nv_bfloat16& l) {
    h = __float2bfloat16(v);
    l = __float2bfloat16(v - __bfloat162float(h));
}

#define ASTR 72

// ===========================================================================
// 3x3 conv (pad=1) as implicit GEMM on mma.sync, bf16x3 split (validated R10)
// ===========================================================================
#define CONV_SMEM 55296

__global__ __launch_bounds__(256)
void conv3x3_mma(const float* __restrict__ W, const float* __restrict__ X)
{
    extern __shared__ char smem[];
    __nv_bfloat16* sAhi = (__nv_bfloat16*)smem;                 // 128*72
    __nv_bfloat16* sAlo = sAhi + 128 * ASTR;
    __nv_bfloat16* sBhi = sAlo + 128 * ASTR;                    // 64*72
    __nv_bfloat16* sBlo = sBhi + 64 * ASTR;
    const uint32_t uAhi = smem_u32(sAhi), uAlo = smem_u32(sAlo);
    const uint32_t uBhi = smem_u32(sBhi), uBlo = smem_u32(sBlo);

    const int t    = threadIdx.x;
    const int warp = t >> 5, lane = t & 31;
    const int wm   = warp & 3;
    const int wn   = warp >> 2;
    const int n0   = blockIdx.x * 64;
    const int m0   = blockIdx.y * 128;
    const float* Xp = X    + (size_t)blockIdx.z * C_IN * NPIX;
    float*       Cp = g_KV + (size_t)blockIdx.z * MKV  * NPIX;

    const int arow  = (lane & 15);
    const int acolb = (lane >> 4) * 16;
    const int brow  = (lane & 7) + ((lane >> 4) << 3);
    const int bcolb = ((lane >> 3) & 1) * 16;

    float acc[2][4][4] = {};

    for (int p = 0; p < 36; p++) {
        const int k0 = p * 64;
        #pragma unroll
        for (int r = 0; r < 16; r++) {
            int i  = t + r * 256;
            int kp = i & 31, m = i >> 5;
            float2 w2 = *(const float2*)(W + (size_t)(m0 + m) * KCONV + k0 + 2 * kp);
            __nv_bfloat162 hi, lo;
            split2(w2.x, hi.x, lo.x);
            split2(w2.y, hi.y, lo.y);
            *(__nv_bfloat162*)(sAhi + m * ASTR + 2 * kp) = hi;
            *(__nv_bfloat162*)(sAlo + m * ASTR + 2 * kp) = lo;
        }
        #pragma unroll
        for (int r = 0; r < 8; r++) {
            int i  = t + r * 256;
            int kp = i & 31, nn = i >> 5;
            int n = n0 + nn, py = n >> 5, px = n & 31;
            float v0, v1;
            {
                int kg = k0 + 2 * kp;
                int ci = kg / 9, tap = kg - ci * 9;
                int y = py + tap / 3 - 1, x = px + tap - (tap / 3) * 3 - 1;
                v0 = ((unsigned)y < 32u && (unsigned)x < 32u)
                     ? Xp[(size_t)ci * NPIX + (y << 5) + x] : 0.f;
            }
            {
                int kg = k0 + 2 * kp + 1;
                int ci = kg / 9, tap = kg - ci * 9;
                int y = py + tap / 3 - 1, x = px + tap - (tap / 3) * 3 - 1;
                v1 = ((unsigned)y < 32u && (unsigned)x < 32u)
                     ? Xp[(size_t)ci * NPIX + (y << 5) + x] : 0.f;
            }
            __nv_bfloat162 hi, lo;
            split2(v0, hi.x, lo.x);
            split2(v1, hi.y, lo.y);
            *(__nv_bfloat162*)(sBhi + nn * ASTR + 2 * kp) = hi;
            *(__nv_bfloat162*)(sBlo + nn * ASTR + 2 * kp) = lo;
        }
        __syncthreads();

        #pragma unroll
        for (int ks = 0; ks < 4; ks++) {
            const int kb = ks * 32;
            uint32_t ah[2][4], al[2][4], bh[2][4], bl[2][4];
            #pragma unroll
            for (int mt = 0; mt < 2; mt++) {
                uint32_t off = (uint32_t)((wm * 32 + mt * 16 + arow) * ASTR) * 2
                             + kb + acolb;
                ldmx4(ah[mt], uAhi + off);
                ldmx4(al[mt], uAlo + off);
            }
            #pragma unroll
            for (int nt2 = 0; nt2 < 2; nt2++) {
                uint32_t off = (uint32_t)((wn * 32 + nt2 * 16 + brow) * ASTR) * 2
                             + kb + bcolb;
                ldmx4(bh[nt2], uBhi + off);
                ldmx4(bl[nt2], uBlo + off);
            }
            #pragma unroll
            for (int mt = 0; mt < 2; mt++)
                #pragma unroll
                for (int nt = 0; nt < 4; nt++) {
                    uint32_t b0h = bh[nt >> 1][(nt & 1) * 2];
                    uint32_t b1h = bh[nt >> 1][(nt & 1) * 2 + 1];
                    uint32_t b0l = bl[nt >> 1][(nt & 1) * 2];
                    uint32_t b1l = bl[nt >> 1][(nt & 1) * 2 + 1];
                    mma_bf16(acc[mt][nt], ah[mt], b0h, b1h);
                    mma_bf16(acc[mt][nt], ah[mt], b0l, b1l);
                    mma_bf16(acc[mt][nt], al[mt], b0h, b1h);
                }
        }
        __syncthreads();
    }

    float* sO = (float*)smem;   // [128][66]
    #pragma unroll
    for (int mt = 0; mt < 2; mt++)
        #pragma unroll
        for (int nt = 0; nt < 4; nt++) {
            int row = wm * 32 + mt * 16 + (lane >> 2);
            int col = wn * 32 + nt * 8 + (lane & 3) * 2;
            *(float2*)(sO + row * 66 + col) =
                make_float2(acc[mt][nt][0], acc[mt][nt][1]);
            *(float2*)(sO + (row + 8) * 66 + col) =
                make_float2(acc[mt][nt][2], acc[mt][nt][3]);
        }
    __syncthreads();
    for (int i = t; i < 8192; i += 256) {
        int m = i >> 6, c = i & 63;
        Cp[(size_t)(m0 + m) * NPIX + n0 + c] = sO[m * 66 + c];
    }
}

// ===========================================================================
// 1x1 conv GEMM on mma.sync bf16x3:
//   C[z][m][n] = sum_k A[m][k] * B[z][k][n]  (+ bias[m])
// Same tile scheme as conv3x3_mma, B transposed on load (sB[n][k]).
// ===========================================================================
template<int BIAS>
__global__ __launch_bounds__(256)
void gemm_mma(const float* __restrict__ A, const float* __restrict__ Bm,
              float* __restrict__ Cm, const float* __restrict__ bias,
              int M, int N, int K)
{
    extern __shared__ char smem[];
    __nv_bfloat16* sAhi = (__nv_bfloat16*)smem;
    __nv_bfloat16* sAlo = sAhi + 128 * ASTR;
    __nv_bfloat16* sBhi = sAlo + 128 * ASTR;
    __nv_bfloat16* sBlo = sBhi + 64 * ASTR;
    const uint32_t uAhi = smem_u32(sAhi), uAlo = smem_u32(sAlo);
    const uint32_t uBhi = smem_u32(sBhi), uBlo = smem_u32(sBlo);

    const int t    = threadIdx.x;
    const int warp = t >> 5, lane = t & 31;
    const int wm   = warp & 3;
    const int wn   = warp >> 2;
    const int n0   = blockIdx.x * 64;
    const int m0   = blockIdx.y * 128;
    const float* Bp = Bm + (size_t)blockIdx.z * K * N;
    float*       Cp = Cm + (size_t)blockIdx.z * M * N;

    const int arow  = (lane & 15);
    const int acolb = (lane >> 4) * 16;
    const int brow  = (lane & 7) + ((lane >> 4) << 3);
    const int bcolb = ((lane >> 3) & 1) * 16;

    float acc[2][4][4] = {};

    for (int k0 = 0; k0 < K; k0 += 64) {
        #pragma unroll
        for (int r = 0; r < 16; r++) {
            int i  = t + r * 256;
            int kp = i & 31, m = i >> 5;
            float2 w2 = *(const float2*)(A + (size_t)(m0 + m) * K + k0 + 2 * kp);
            __nv_bfloat162 hi, lo;
            split2(w2.x, hi.x, lo.x);
            split2(w2.y, hi.y, lo.y);
            *(__nv_bfloat162*)(sAhi + m * ASTR + 2 * kp) = hi;
            *(__nv_bfloat162*)(sAlo + m * ASTR + 2 * kp) = lo;
        }
        #pragma unroll
        for (int r = 0; r < 16; r++) {
            int i  = t + r * 256;
            int nn = i & 63, kk = i >> 6;   // coalesced read along n
            float v = Bp[(size_t)(k0 + kk) * N + n0 + nn];
            __nv_bfloat16 h, l;
            split2(v, h, l);
            sBhi[nn * ASTR + kk] = h;
            sBlo[nn * ASTR + kk] = l;
        }
        __syncthreads();

        #pragma unroll
        for (int ks = 0; ks < 4; ks++) {
            const int kb = ks * 32;
            uint32_t ah[2][4], al[2][4], bh[2][4], bl[2][4];
            #pragma unroll
            for (int mt = 0; mt < 2; mt++) {
                uint32_t off = (uint32_t)((wm * 32 + mt * 16 + arow) * ASTR) * 2
                             + kb + acolb;
                ldmx4(ah[mt], uAhi + off);
                ldmx4(al[mt], uAlo + off);
            }
            #pragma unroll
            for (int nt2 = 0; nt2 < 2; nt2++) {
                uint32_t off = (uint32_t)((wn * 32 + nt2 * 16 + brow) * ASTR) * 2
                             + kb + bcolb;
                ldmx4(bh[nt2], uBhi + off);
                ldmx4(bl[nt2], uBlo + off);
            }
            #pragma unroll
            for (int mt = 0; mt < 2; mt++)
                #pragma unroll
                for (int nt = 0; nt < 4; nt++) {
                    uint32_t b0h = bh[nt >> 1][(nt & 1) * 2];
                    uint32_t b1h = bh[nt >> 1][(nt & 1) * 2 + 1];
                    uint32_t b0l = bl[nt >> 1][(nt & 1) * 2];
                    uint32_t b1l = bl[nt >> 1][(nt & 1) * 2 + 1];
                    mma_bf16(acc[mt][nt], ah[mt], b0h, b1h);
                    mma_bf16(acc[mt][nt], ah[mt], b0l, b1l);
                    mma_bf16(acc[mt][nt], al[mt], b0h, b1h);
                }
        }
        __syncthreads();
    }

    float* sO = (float*)smem;   // [128][66]
    #pragma unroll
    for (int mt = 0; mt < 2; mt++)
        #pragma unroll
        for (int nt = 0; nt < 4; nt++) {
            int row = wm * 32 + mt * 16 + (lane >> 2);
            int col = wn * 32 + nt * 8 + (lane & 3) * 2;
            *(float2*)(sO + row * 66 + col) =
                make_float2(acc[mt][nt][0], acc[mt][nt][1]);
            *(float2*)(sO + (row + 8) * 66 + col) =
                make_float2(acc[mt][nt][2], acc[mt][nt][3]);
        }
    __syncthreads();
    for (int i = t; i < 8192; i += 256) {
        int m = i >> 6, c = i & 63;
        float bv = BIAS ? bias[m0 + m] : 0.f;
        Cp[(size_t)(m0 + m) * NPIX + n0 + c] = sO[m * 66 + c] + bv;
    }
}

// ===========================================================================
// Flash attention on mma.sync bf16x3: one CTA per (b*h, 64-query tile).
// S = (Q*0.125)·K^T via mma (scale folded into Q, exact: power of two).
// Softmax unchanged (1 thread/row), P re-split hi/lo, O += P·V via mma.
// Layouts: g_KV is [d][pixel] channel-major == B[n][k] for P·V directly;
// K transposed on load to sK[key][d] == B[n][k] for S.
// ===========================================================================
#define FA_SMEM (8 * 64 * ASTR * 2 + 64 * 68 * 4 + 3 * 64 * 4)   // 91904 B

__global__ __launch_bounds__(256)
void flash_attn_mma(const float* __restrict__ Q, const float* __restrict__ KV,
                    float* __restrict__ AO)
{
    extern __shared__ char smc[];
    __nv_bfloat16* sb = (__nv_bfloat16*)smc;
    __nv_bfloat16* sQh = sb;
    __nv_bfloat16* sQl = sQh + 64 * ASTR;
    __nv_bfloat16* sKh = sQl + 64 * ASTR;
    __nv_bfloat16* sKl = sKh + 64 * ASTR;
    __nv_bfloat16* sVh = sKl + 64 * ASTR;
    __nv_bfloat16* sVl = sVh + 64 * ASTR;
    __nv_bfloat16* sPh = sVl + 64 * ASTR;
    __nv_bfloat16* sPl = sPh + 64 * ASTR;
    float* sS = (float*)(smc + 8 * 64 * ASTR * 2);   // [64][68]
    float* rm = sS + 64 * 68;
    float* rl = rm + 64;
    float* rf = rl + 64;
    const uint32_t uQh = smem_u32(sQh), uQl = smem_u32(sQl);
    const uint32_t uKh = smem_u32(sKh), uKl = smem_u32(sKl);
    const uint32_t uVh = smem_u32(sVh), uVl = smem_u32(sVl);
    const uint32_t uPh = smem_u32(sPh), uPl = smem_u32(sPl);

    const int t    = threadIdx.x;
    const int warp = t >> 5, lane = t & 31;
    const int wm   = warp & 3;       // q-row block of 16
    const int wn   = warp >> 2;      // col block of 32
    const int q0   = blockIdx.x * 64;
    const int bh   = blockIdx.y;
    const int b    = bh >> 3, h = bh & 7;

    const float* qb = Q  + ((size_t)b * INNER + h * DH) * NPIX;
    const float* kb = KV + ((size_t)b * MKV   + h * DH) * NPIX;
    const float* vb = KV + ((size_t)b * MKV + INNER + h * DH) * NPIX;
    float*       ob = AO + ((size_t)b * INNER + h * DH) * NPIX;

    const int arow  = (lane & 15);
    const int acolb = (lane >> 4) * 16;
    const int brow  = (lane & 7) + ((lane >> 4) << 3);
    const int bcolb = ((lane >> 3) & 1) * 16;

    // Q load (scale folded in, exact), transposed to [q][d]
    for (int idx = t; idx < 4096; idx += 256) {
        int d = idx >> 6, qi = idx & 63;
        float v = qb[(size_t)d * NPIX + q0 + qi] * 0.125f;
        __nv_bfloat16 hh, ll;
        split2(v, hh, ll);
        sQh[qi * ASTR + d] = hh;
        sQl[qi * ASTR + d] = ll;
    }
    if (t < 64) { rm[t] = -1e30f; rl[t] = 0.f; }

    float accO[4][4] = {};   // 1 m-tile x 4 n-tiles per warp

    for (int k0 = 0; k0 < NPIX; k0 += 64) {
        // K: transpose to [key][d]; V: direct [d][key]
        for (int idx = t; idx < 4096; idx += 256) {
            int d = idx >> 6, ki = idx & 63;
            float kvv = kb[(size_t)d * NPIX + k0 + ki];
            __nv_bfloat16 hh, ll;
            split2(kvv, hh, ll);
            sKh[ki * ASTR + d] = hh;
            sKl[ki * ASTR + d] = ll;
            float vv = vb[(size_t)d * NPIX + k0 + ki];
            split2(vv, hh, ll);
            sVh[d * ASTR + ki] = hh;
            sVl[d * ASTR + ki] = ll;
        }
        __syncthreads();

        // S = Qs · K^T  (fp32 frag, bf16x3)
        float s[4][4] = {};
        #pragma unroll
        for (int ks = 0; ks < 4; ks++) {
            const int kbyte = ks * 32;
            uint32_t ah[4], al[4], bhv[2][4], blv[2][4];
            {
                uint32_t off = (uint32_t)((wm * 16 + arow) * ASTR) * 2 + kbyte + acolb;
                ldmx4(ah, uQh + off);
                ldmx4(al, uQl + off);
            }
            #pragma unroll
            for (int nt2 = 0; nt2 < 2; nt2++) {
                uint32_t off = (uint32_t)((wn * 32 + nt2 * 16 + brow) * ASTR) * 2
                             + kbyte + bcolb;
                ldmx4(bhv[nt2], uKh + off);
                ldmx4(blv[nt2], uKl + off);
            }
            #pragma unroll
            for (int nt = 0; nt < 4; nt++) {
                uint32_t b0h = bhv[nt >> 1][(nt & 1) * 2];
                uint32_t b1h = bhv[nt >> 1][(nt & 1) * 2 + 1];
                uint32_t b0l = blv[nt >> 1][(nt & 1) * 2];
                uint32_t b1l = blv[nt >> 1][(nt & 1) * 2 + 1];
                mma_bf16(s[nt], ah, b0h, b1h);
                mma_bf16(s[nt], ah, b0l, b1l);
                mma_bf16(s[nt], al, b0h, b1h);
            }
        }
        {
            int row = wm * 16 + (lane >> 2);
            #pragma unroll
            for (int nt = 0; nt < 4; nt++) {
                int col = wn * 32 + nt * 8 + (lane & 3) * 2;
                *(float2*)(sS + row * 68 + col)       = make_float2(s[nt][0], s[nt][1]);
                *(float2*)(sS + (row + 8) * 68 + col) = make_float2(s[nt][2], s[nt][3]);
            }
        }
        __syncthreads();

        // Online softmax (thread r = row r), writes P hi/lo bf16
        if (t < 64) {
            float mo = rm[t];
            float mx = mo;
            #pragma unroll 8
            for (int j = 0; j < 64; j++) mx = fmaxf(mx, sS[t * 68 + j]);
            float sum = 0.f;
            #pragma unroll 8
            for (int j = 0; j < 64; j++) {
                float e = expf(sS[t * 68 + j] - mx);
                sum += e;
                __nv_bfloat16 hh, ll;
                split2(e, hh, ll);
                sPh[t * ASTR + j] = hh;
                sPl[t * ASTR + j] = ll;
            }
            float f = expf(mo - mx);
            rf[t] = f;
            rl[t] = rl[t] * f + sum;
            rm[t] = mx;
        }
        __syncthreads();

        // Rescale O, then O += P · V   (A = P[q][key], B = V[d][key])
        {
            float f0 = rf[wm * 16 + (lane >> 2)];
            float f1 = rf[wm * 16 + (lane >> 2) + 8];
            #pragma unroll
            for (int nt = 0; nt < 4; nt++) {
                accO[nt][0] *= f0; accO[nt][1] *= f0;
                accO[nt][2] *= f1; accO[nt][3] *= f1;
            }
        }
        #pragma unroll
        for (int ks = 0; ks < 4; ks++) {
            const int kbyte = ks * 32;
            uint32_t ph[4], pl[4], bhv[2][4], blv[2][4];
            {
                uint32_t off = (uint32_t)((wm * 16 + arow) * ASTR) * 2 + kbyte + acolb;
                ldmx4(ph, uPh + off);
                ldmx4(pl, uPl + off);
            }
            #pragma unroll
            for (int nt2 = 0; nt2 < 2; nt2++) {
                uint32_t off = (uint32_t)((wn * 32 + nt2 * 16 + brow) * ASTR) * 2
                             + kbyte + bcolb;
                ldmx4(bhv[nt2], uVh + off);
                ldmx4(blv[nt2], uVl + off);
            }
            #pragma unroll
            for (int nt = 0; nt < 4; nt++) {
                uint32_t b0h = bhv[nt >> 1][(nt & 1) * 2];
                uint32_t b1h = bhv[nt >> 1][(nt & 1) * 2 + 1];
                uint32_t b0l = blv[nt >> 1][(nt & 1) * 2];
                uint32_t b1l = blv[nt >> 1][(nt & 1) * 2 + 1];
                mma_bf16(accO[nt], ph, b0h, b1h);
                mma_bf16(accO[nt], ph, b0l, b1l);
                mma_bf16(accO[nt], pl, b0h, b1h);
            }
        }
        __syncthreads();
    }

    // Epilogue: normalize, exact GELU, stage, coalesced transposed writeback
    {
        int row0 = wm * 16 + (lane >> 2);
        float i0 = 1.f / rl[row0];
        float i1 = 1.f / rl[row0 + 8];
        #pragma unroll
        for (int nt = 0; nt < 4; nt++) {
            int col = wn * 32 + nt * 8 + (lane & 3) * 2;
            #pragma unroll
            for (int e = 0; e < 4; e++) {
                float v = accO[nt][e] * (e < 2 ? i0 : i1);
                float g = 0.5f * v * (1.f + erff(v * 0.70710678118654752f));
                sS[(row0 + (e >> 1) * 8) * 68 + col + (e & 1)] = g;
            }
        }
    }
    __syncthreads();
    for (int idx = t; idx < 4096; idx += 256) {
        int d = idx >> 6, qi = idx & 63;
        ob[(size_t)d * NPIX + q0 + qi] = sS[qi * 68 + d];
    }
}

// ---------------------------------------------------------------------------
extern "C" void kernel_launch(void* const* d_in, const int* in_sizes, int n_in,
                              void* d_out, int out_size)
{
    const float* x    = (const float*)d_in[0];  // [8,256,32,32]
    const float* Wq   = (const float*)d_in[1];  // [512,256,1,1]
    const float* Wkv  = (const float*)d_in[2];  // [1024,256,3,3]
    const float* Wout = (const float*)d_in[3];  // [256,512,1,1]
    const float* bout = (const float*)d_in[4];  // [256]
    float* out = (float*)d_out;                 // [8,256,32,32]

    float *qp, *kvp, *aop;
    cudaGetSymbolAddress((void**)&qp,  g_Q);
    cudaGetSymbolAddress((void**)&kvp, g_KV);
    cudaGetSymbolAddress((void**)&aop, g_AO);

    dim3 blk(256);

    // 1) Q = Wq * x        (M=512, N=1024, K=256, per batch) — mma
    cudaFuncSetAttribute(gemm_mma<0>,
                         cudaFuncAttributeMaxDynamicSharedMemorySize, CONV_SMEM);
    gemm_mma<0><<<dim3(16, 4, BATCH), blk, CONV_SMEM>>>(
        Wq, x, qp, nullptr, INNER, NPIX, C_IN);

    // 2) KV = conv3x3(x) on mma bf16x3  (M=1024, N=1024, K=2304, per batch)
    cudaFuncSetAttribute(conv3x3_mma,
                         cudaFuncAttributeMaxDynamicSharedMemorySize, CONV_SMEM);
    conv3x3_mma<<<dim3(16, 8, BATCH), blk, CONV_SMEM>>>(Wkv, x);

    // 3) Flash attention + GELU on mma bf16x3
    cudaFuncSetAttribute(flash_attn_mma,
                         cudaFuncAttributeMaxDynamicSharedMemorySize, FA_SMEM);
    flash_attn_mma<<<dim3(16, BATCH * HEADS), blk, FA_SMEM>>>(qp, kvp, aop);

    // 4) out = Wout * gelu_attn + bout   (M=256, N=1024, K=512, per batch) — mma
    cudaFuncSetAttribute(gemm_mma<1>,
                         cudaFuncAttributeMaxDynamicSharedMemorySize, CONV_SMEM);
    gemm_mma<1><<<dim3(16, 2, BATCH), blk, CONV_SMEM>>>(
        Wout, aop, out, bout, 256, NPIX, INNER);
}

// round 12
// speedup vs baseline: 2.0424x; 1.2176x over previous
#include <cuda_runtime.h>
#include <cuda_bf16.h>
#include <cstdint>
#include <math.h>

// Problem constants (fixed shapes from reference)
#define BATCH  8
#define C_IN   256
#define NPIX   1024   // 32*32
#define INNER  512    // heads*dim_head
#define HEADS  8
#define DH     64
#define KCONV  2304   // 256*9
#define MKV    1024   // 2*INNER

// ---------------------------------------------------------------------------
// Packed bf16 hi/lo format: uint32 = hi.bits | lo.bits<<16, where
// hi = bf16(v), lo = bf16(v - float(hi)).  hi+lo ~ v to ~2^-16 relative.
// All weights and intermediates live in this format; consumers split with
// __byte_perm (no float converts in any hot loop).
// ---------------------------------------------------------------------------
__device__ uint32_t g_Wqp [(size_t)INNER * C_IN];        // Wq * 0.125 folded
__device__ uint32_t g_Wkvp[(size_t)MKV * KCONV];
__device__ uint32_t g_Wop [(size_t)C_IN * INNER];
__device__ uint32_t g_Xp  [(size_t)BATCH * C_IN * NPIX];
__device__ uint32_t g_Qp  [(size_t)BATCH * INNER * NPIX];
__device__ uint32_t g_KVp [(size_t)BATCH * MKV * NPIX];
__device__ uint32_t g_AOp [(size_t)BATCH * INNER * NPIX];

__device__ __forceinline__ uint32_t packsplit(float v) {
    __nv_bfloat16 h = __float2bfloat16(v);
    __nv_bfloat16 l = __float2bfloat16(v - __bfloat162float(h));
    return (uint32_t)__bfloat16_as_ushort(h)
         | ((uint32_t)__bfloat16_as_ushort(l) << 16);
}
__device__ __forceinline__ void split2(float v, __nv_bfloat16& h, __nv_bfloat16& l) {
    h = __float2bfloat16(v);
    l = __float2bfloat16(v - __bfloat162float(h));
}

__global__ __launch_bounds__(256)
void split_pack4(const float4* __restrict__ in, uint4* __restrict__ out,
                 int n4, float scale)
{
    int i = blockIdx.x * 256 + threadIdx.x;
    if (i < n4) {
        float4 v = in[i];
        uint4 o;
        o.x = packsplit(v.x * scale);
        o.y = packsplit(v.y * scale);
        o.z = packsplit(v.z * scale);
        o.w = packsplit(v.w * scale);
        out[i] = o;
    }
}

// ===========================================================================
// mma.sync helpers (HMMA — supported on plain sm_103; tcgen05 is NOT:
// the harness PTX target is sm_103 without the 'a' suffix)
// ===========================================================================
__device__ __forceinline__ uint32_t smem_u32(const void* p) {
    uint32_t a;
    asm("{ .reg .u64 t; cvta.to.shared.u64 t, %1; cvt.u32.u64 %0, t; }"
        : "=r"(a) : "l"(p));
    return a;
}
__device__ __forceinline__ void ldmx4(uint32_t* r, uint32_t addr) {
    asm volatile("ldmatrix.sync.aligned.m8n8.x4.shared.b16 {%0,%1,%2,%3}, [%4];"
        : "=r"(r[0]), "=r"(r[1]), "=r"(r[2]), "=r"(r[3]) : "r"(addr));
}
__device__ __forceinline__ void mma_bf16(float* c, const uint32_t* a,
                                         uint32_t b0, uint32_t b1) {
    asm volatile(
        "mma.sync.aligned.m16n8k16.row.col.f32.bf16.bf16.f32 "
        "{%0,%1,%2,%3}, {%4,%5,%6,%7}, {%8,%9}, {%0,%1,%2,%3};"
        : "+f"(c[0]), "+f"(c[1]), "+f"(c[2]), "+f"(c[3])
        : "r"(a[0]), "r"(a[1]), "r"(a[2]), "r"(a[3]), "r"(b0), "r"(b1));
}

#define ASTR 72

// ===========================================================================
// 3x3 conv (pad=1) as implicit GEMM on mma.sync bf16x3, packed-split inputs.
// CTA: 128 co x 64 pix; K=2304 in 36 panels of 64.
// ===========================================================================
#define CONV_SMEM 55296

__global__ __launch_bounds__(256)
void conv3x3_mma(const uint32_t* __restrict__ W, const uint32_t* __restrict__ X,
                 uint32_t* __restrict__ KVp)
{
    extern __shared__ char smem[];
    uint16_t* sAh = (uint16_t*)smem;                 // 128*72
    uint16_t* sAl = sAh + 128 * ASTR;
    uint16_t* sBh = sAl + 128 * ASTR;                // 64*72
    uint16_t* sBl = sBh + 64 * ASTR;
    const uint32_t uAh = smem_u32(sAh), uAl = smem_u32(sAl);
    const uint32_t uBh = smem_u32(sBh), uBl = smem_u32(sBl);

    const int t    = threadIdx.x;
    const int warp = t >> 5, lane = t & 31;
    const int wm   = warp & 3;
    const int wn   = warp >> 2;
    const int n0   = blockIdx.x * 64;
    const int m0   = blockIdx.y * 128;
    const uint32_t* Xp = X   + (size_t)blockIdx.z * C_IN * NPIX;
    uint32_t*       Cp = KVp + (size_t)blockIdx.z * MKV  * NPIX;

    const int arow  = (lane & 15);
    const int acolb = (lane >> 4) * 16;
    const int brow  = (lane & 7) + ((lane >> 4) << 3);
    const int bcolb = ((lane >> 3) & 1) * 16;

    float acc[2][4][4] = {};

    for (int p = 0; p < 36; p++) {
        const int k0 = p * 64;
        // A: 128x64 packed words = 2048 uint4
        #pragma unroll
        for (int r = 0; r < 8; r++) {
            int i  = t + r * 256;
            int m = i >> 4, kq = (i & 15) * 4;
            uint4 w = *(const uint4*)(W + (size_t)(m0 + m) * KCONV + k0 + kq);
            uint32_t h0 = __byte_perm(w.x, w.y, 0x5410);
            uint32_t l0 = __byte_perm(w.x, w.y, 0x7632);
            uint32_t h1 = __byte_perm(w.z, w.w, 0x5410);
            uint32_t l1 = __byte_perm(w.z, w.w, 0x7632);
            *(uint2*)(sAh + m * ASTR + kq) = make_uint2(h0, h1);
            *(uint2*)(sAl + m * ASTR + kq) = make_uint2(l0, l1);
        }
        // B: im2col gather, 64x64 packed words
        #pragma unroll
        for (int r = 0; r < 16; r++) {
            int i  = t + r * 256;
            int kk = i & 63, nn = i >> 6;
            int kg = k0 + kk;
            int ci = kg / 9, tap = kg - ci * 9;
            int n = n0 + nn;
            int y = (n >> 5) + tap / 3 - 1;
            int x = (n & 31) + tap - (tap / 3) * 3 - 1;
            uint32_t w = 0;
            if ((unsigned)y < 32u && (unsigned)x < 32u)
                w = Xp[(size_t)ci * NPIX + (y << 5) + x];
            sBh[nn * ASTR + kk] = (uint16_t)w;
            sBl[nn * ASTR + kk] = (uint16_t)(w >> 16);
        }
        __syncthreads();

        #pragma unroll
        for (int ks = 0; ks < 4; ks++) {
            const int kb = ks * 32;
            uint32_t ah[2][4], al[2][4], bh[2][4], bl[2][4];
            #pragma unroll
            for (int mt = 0; mt < 2; mt++) {
                uint32_t off = (uint32_t)((wm * 32 + mt * 16 + arow) * ASTR) * 2
                             + kb + acolb;
                ldmx4(ah[mt], uAh + off);
                ldmx4(al[mt], uAl + off);
            }
            #pragma unroll
            for (int nt2 = 0; nt2 < 2; nt2++) {
                uint32_t off = (uint32_t)((wn * 32 + nt2 * 16 + brow) * ASTR) * 2
                             + kb + bcolb;
                ldmx4(bh[nt2], uBh + off);
                ldmx4(bl[nt2], uBl + off);
            }
            #pragma unroll
            for (int mt = 0; mt < 2; mt++)
                #pragma unroll
                for (int nt = 0; nt < 4; nt++) {
                    uint32_t b0h = bh[nt >> 1][(nt & 1) * 2];
                    uint32_t b1h = bh[nt >> 1][(nt & 1) * 2 + 1];
                    uint32_t b0l = bl[nt >> 1][(nt & 1) * 2];
                    uint32_t b1l = bl[nt >> 1][(nt & 1) * 2 + 1];
                    mma_bf16(acc[mt][nt], ah[mt], b0h, b1h);
                    mma_bf16(acc[mt][nt], ah[mt], b0l, b1l);
                    mma_bf16(acc[mt][nt], al[mt], b0h, b1h);
                }
        }
        __syncthreads();
    }

    float* sO = (float*)smem;   // [128][66]
    #pragma unroll
    for (int mt = 0; mt < 2; mt++)
        #pragma unroll
        for (int nt = 0; nt < 4; nt++) {
            int row = wm * 32 + mt * 16 + (lane >> 2);
            int col = wn * 32 + nt * 8 + (lane & 3) * 2;
            *(float2*)(sO + row * 66 + col) =
                make_float2(acc[mt][nt][0], acc[mt][nt][1]);
            *(float2*)(sO + (row + 8) * 66 + col) =
                make_float2(acc[mt][nt][2], acc[mt][nt][3]);
        }
    __syncthreads();
    for (int i = t; i < 8192; i += 256) {
        int m = i >> 6, c = i & 63;
        Cp[(size_t)(m0 + m) * NPIX + n0 + c] = packsplit(sO[m * 66 + c]);
    }
}

// ===========================================================================
// 1x1 conv GEMM on mma.sync bf16x3, packed inputs.
// PACKED=1: write packed hi/lo uint32 (no bias). PACKED=0: float out + bias.
// ===========================================================================
template<int PACKED>
__global__ __launch_bounds__(256)
void gemm_mma(const uint32_t* __restrict__ A, const uint32_t* __restrict__ Bm,
              void* __restrict__ Cm, const float* __restrict__ bias,
              int M, int N, int K)
{
    extern __shared__ char smem[];
    uint16_t* sAh = (uint16_t*)smem;
    uint16_t* sAl = sAh + 128 * ASTR;
    uint16_t* sBh = sAl + 128 * ASTR;
    uint16_t* sBl = sBh + 64 * ASTR;
    const uint32_t uAh = smem_u32(sAh), uAl = smem_u32(sAl);
    const uint32_t uBh = smem_u32(sBh), uBl = smem_u32(sBl);

    const int t    = threadIdx.x;
    const int warp = t >> 5, lane = t & 31;
    const int wm   = warp & 3;
    const int wn   = warp >> 2;
    const int n0   = blockIdx.x * 64;
    const int m0   = blockIdx.y * 128;
    const uint32_t* Bp = Bm + (size_t)blockIdx.z * K * N;

    const int arow  = (lane & 15);
    const int acolb = (lane >> 4) * 16;
    const int brow  = (lane & 7) + ((lane >> 4) << 3);
    const int bcolb = ((lane >> 3) & 1) * 16;

    float acc[2][4][4] = {};

    for (int k0 = 0; k0 < K; k0 += 64) {
        #pragma unroll
        for (int r = 0; r < 8; r++) {
            int i  = t + r * 256;
            int m = i >> 4, kq = (i & 15) * 4;
            uint4 w = *(const uint4*)(A + (size_t)(m0 + m) * K + k0 + kq);
            uint32_t h0 = __byte_perm(w.x, w.y, 0x5410);
            uint32_t l0 = __byte_perm(w.x, w.y, 0x7632);
            uint32_t h1 = __byte_perm(w.z, w.w, 0x5410);
            uint32_t l1 = __byte_perm(w.z, w.w, 0x7632);
            *(uint2*)(sAh + m * ASTR + kq) = make_uint2(h0, h1);
            *(uint2*)(sAl + m * ASTR + kq) = make_uint2(l0, l1);
        }
        // B: [k][n] global -> sB[n][k] transposed; vector load along n
        #pragma unroll
        for (int r = 0; r < 4; r++) {
            int i  = t + r * 256;
            int kk = i >> 4, nq = (i & 15) * 4;
            uint4 w = *(const uint4*)(Bp + (size_t)(k0 + kk) * N + n0 + nq);
            sBh[(nq + 0) * ASTR + kk] = (uint16_t)w.x;
            sBl[(nq + 0) * ASTR + kk] = (uint16_t)(w.x >> 16);
            sBh[(nq + 1) * ASTR + kk] = (uint16_t)w.y;
            sBl[(nq + 1) * ASTR + kk] = (uint16_t)(w.y >> 16);
            sBh[(nq + 2) * ASTR + kk] = (uint16_t)w.z;
            sBl[(nq + 2) * ASTR + kk] = (uint16_t)(w.z >> 16);
            sBh[(nq + 3) * ASTR + kk] = (uint16_t)w.w;
            sBl[(nq + 3) * ASTR + kk] = (uint16_t)(w.w >> 16);
        }
        __syncthreads();

        #pragma unroll
        for (int ks = 0; ks < 4; ks++) {
            const int kb = ks * 32;
            uint32_t ah[2][4], al[2][4], bh[2][4], bl[2][4];
            #pragma unroll
            for (int mt = 0; mt < 2; mt++) {
                uint32_t off = (uint32_t)((wm * 32 + mt * 16 + arow) * ASTR) * 2
                             + kb + acolb;
                ldmx4(ah[mt], uAh + off);
                ldmx4(al[mt], uAl + off);
            }
            #pragma unroll
            for (int nt2 = 0; nt2 < 2; nt2++) {
                uint32_t off = (uint32_t)((wn * 32 + nt2 * 16 + brow) * ASTR) * 2
                             + kb + bcolb;
                ldmx4(bh[nt2], uBh + off);
                ldmx4(bl[nt2], uBl + off);
            }
            #pragma unroll
            for (int mt = 0; mt < 2; mt++)
                #pragma unroll
                for (int nt = 0; nt < 4; nt++) {
                    uint32_t b0h = bh[nt >> 1][(nt & 1) * 2];
                    uint32_t b1h = bh[nt >> 1][(nt & 1) * 2 + 1];
                    uint32_t b0l = bl[nt >> 1][(nt & 1) * 2];
                    uint32_t b1l = bl[nt >> 1][(nt & 1) * 2 + 1];
                    mma_bf16(acc[mt][nt], ah[mt], b0h, b1h);
                    mma_bf16(acc[mt][nt], ah[mt], b0l, b1l);
                    mma_bf16(acc[mt][nt], al[mt], b0h, b1h);
                }
        }
        __syncthreads();
    }

    float* sO = (float*)smem;   // [128][66]
    #pragma unroll
    for (int mt = 0; mt < 2; mt++)
        #pragma unroll
        for (int nt = 0; nt < 4; nt++) {
            int row = wm * 32 + mt * 16 + (lane >> 2);
            int col = wn * 32 + nt * 8 + (lane & 3) * 2;
            *(float2*)(sO + row * 66 + col) =
                make_float2(acc[mt][nt][0], acc[mt][nt][1]);
            *(float2*)(sO + (row + 8) * 66 + col) =
                make_float2(acc[mt][nt][2], acc[mt][nt][3]);
        }
    __syncthreads();
    if (PACKED) {
        uint32_t* Cp = (uint32_t*)Cm + (size_t)blockIdx.z * M * N;
        for (int i = t; i < 8192; i += 256) {
            int m = i >> 6, c = i & 63;
            Cp[(size_t)(m0 + m) * N + n0 + c] = packsplit(sO[m * 66 + c]);
        }
    } else {
        float* Cp = (float*)Cm + (size_t)blockIdx.z * M * N;
        for (int i = t; i < 8192; i += 256) {
            int m = i >> 6, c = i & 63;
            Cp[(size_t)(m0 + m) * N + n0 + c] = sO[m * 66 + c] + bias[m0 + m];
        }
    }
}

// ===========================================================================
// Flash attention on mma.sync bf16x3, packed inputs/outputs.
// Scale 0.125 pre-folded into Wq (so Q arrives scaled). Parallel softmax:
// 4 threads per row, __shfl_xor quad reductions, __expf.
// ===========================================================================
#define FA_SMEM (8 * 64 * ASTR * 2 + 64 * 68 * 4 + 3 * 64 * 4)   // 91904 B

__global__ __launch_bounds__(256)
void flash_attn_mma(const uint32_t* __restrict__ Q, const uint32_t* __restrict__ KV,
                    uint32_t* __restrict__ AO)
{
    extern __shared__ char smc[];
    uint16_t* sQh = (uint16_t*)smc;
    uint16_t* sQl = sQh + 64 * ASTR;
    uint16_t* sKh = sQl + 64 * ASTR;
    uint16_t* sKl = sKh + 64 * ASTR;
    uint16_t* sVh = sKl + 64 * ASTR;
    uint16_t* sVl = sVh + 64 * ASTR;
    uint16_t* sPh = sVl + 64 * ASTR;
    uint16_t* sPl = sPh + 64 * ASTR;
    float* sS = (float*)(smc + 8 * 64 * ASTR * 2);   // [64][68]
    float* rm = sS + 64 * 68;
    float* rl = rm + 64;
    float* rf = rl + 64;
    const uint32_t uQh = smem_u32(sQh), uQl = smem_u32(sQl);
    const uint32_t uKh = smem_u32(sKh), uKl = smem_u32(sKl);
    const uint32_t uVh = smem_u32(sVh), uVl = smem_u32(sVl);
    const uint32_t uPh = smem_u32(sPh), uPl = smem_u32(sPl);

    const int t    = threadIdx.x;
    const int warp = t >> 5, lane = t & 31;
    const int wm   = warp & 3;
    const int wn   = warp >> 2;
    const int q0   = blockIdx.x * 64;
    const int bh   = blockIdx.y;
    const int b    = bh >> 3, h = bh & 7;

    const uint32_t* qb = Q  + ((size_t)b * INNER + h * DH) * NPIX;
    const uint32_t* kb = KV + ((size_t)b * MKV   + h * DH) * NPIX;
    const uint32_t* vb = KV + ((size_t)b * MKV + INNER + h * DH) * NPIX;
    uint32_t*       ob = AO + ((size_t)b * INNER + h * DH) * NPIX;

    const int arow  = (lane & 15);
    const int acolb = (lane >> 4) * 16;
    const int brow  = (lane & 7) + ((lane >> 4) << 3);
    const int bcolb = ((lane >> 3) & 1) * 16;

    // Q tile: transpose [d][pix] -> [q][d]
    #pragma unroll
    for (int r = 0; r < 4; r++) {
        int i = t + r * 256;
        int d = i >> 4, pq = (i & 15) * 4;
        uint4 w = *(const uint4*)(qb + (size_t)d * NPIX + q0 + pq);
        sQh[(pq + 0) * ASTR + d] = (uint16_t)w.x;
        sQl[(pq + 0) * ASTR + d] = (uint16_t)(w.x >> 16);
        sQh[(pq + 1) * ASTR + d] = (uint16_t)w.y;
        sQl[(pq + 1) * ASTR + d] = (uint16_t)(w.y >> 16);
        sQh[(pq + 2) * ASTR + d] = (uint16_t)w.z;
        sQl[(pq + 2) * ASTR + d] = (uint16_t)(w.z >> 16);
        sQh[(pq + 3) * ASTR + d] = (uint16_t)w.w;
        sQl[(pq + 3) * ASTR + d] = (uint16_t)(w.w >> 16);
    }
    if (t < 64) { rm[t] = -1e30f; rl[t] = 0.f; }

    float accO[4][4] = {};

    for (int k0 = 0; k0 < NPIX; k0 += 64) {
        // K: transpose to [key][d]; V: direct [d][key] (vectorized)
        #pragma unroll
        for (int r = 0; r < 4; r++) {
            int i = t + r * 256;
            int d = i >> 4, kq = (i & 15) * 4;
            uint4 w = *(const uint4*)(kb + (size_t)d * NPIX + k0 + kq);
            sKh[(kq + 0) * ASTR + d] = (uint16_t)w.x;
            sKl[(kq + 0) * ASTR + d] = (uint16_t)(w.x >> 16);
            sKh[(kq + 1) * ASTR + d] = (uint16_t)w.y;
            sKl[(kq + 1) * ASTR + d] = (uint16_t)(w.y >> 16);
            sKh[(kq + 2) * ASTR + d] = (uint16_t)w.z;
            sKl[(kq + 2) * ASTR + d] = (uint16_t)(w.z >> 16);
            sKh[(kq + 3) * ASTR + d] = (uint16_t)w.w;
            sKl[(kq + 3) * ASTR + d] = (uint16_t)(w.w >> 16);
            uint4 v = *(const uint4*)(vb + (size_t)d * NPIX + k0 + kq);
            uint32_t h0 = __byte_perm(v.x, v.y, 0x5410);
            uint32_t l0 = __byte_perm(v.x, v.y, 0x7632);
            uint32_t h1 = __byte_perm(v.z, v.w, 0x5410);
            uint32_t l1 = __byte_perm(v.z, v.w, 0x7632);
            *(uint2*)(sVh + d * ASTR + kq) = make_uint2(h0, h1);
            *(uint2*)(sVl + d * ASTR + kq) = make_uint2(l0, l1);
        }
        __syncthreads();

        // S = Qs · K^T
        float s[4][4] = {};
        #pragma unroll
        for (int ks = 0; ks < 4; ks++) {
            const int kbyte = ks * 32;
            uint32_t ah[4], al[4], bhv[2][4], blv[2][4];
            {
                uint32_t off = (uint32_t)((wm * 16 + arow) * ASTR) * 2 + kbyte + acolb;
                ldmx4(ah, uQh + off);
                ldmx4(al, uQl + off);
            }
            #pragma unroll
            for (int nt2 = 0; nt2 < 2; nt2++) {
                uint32_t off = (uint32_t)((wn * 32 + nt2 * 16 + brow) * ASTR) * 2
                             + kbyte + bcolb;
                ldmx4(bhv[nt2], uKh + off);
                ldmx4(blv[nt2], uKl + off);
            }
            #pragma unroll
            for (int nt = 0; nt < 4; nt++) {
                uint32_t b0h = bhv[nt >> 1][(nt & 1) * 2];
                uint32_t b1h = bhv[nt >> 1][(nt & 1) * 2 + 1];
                uint32_t b0l = blv[nt >> 1][(nt & 1) * 2];
                uint32_t b1l = blv[nt >> 1][(nt & 1) * 2 + 1];
                mma_bf16(s[nt], ah, b0h, b1h);
                mma_bf16(s[nt], ah, b0l, b1l);
                mma_bf16(s[nt], al, b0h, b1h);
            }
        }
        {
            int row = wm * 16 + (lane >> 2);
            #pragma unroll
            for (int nt = 0; nt < 4; nt++) {
                int col = wn * 32 + nt * 8 + (lane & 3) * 2;
                *(float2*)(sS + row * 68 + col)       = make_float2(s[nt][0], s[nt][1]);
                *(float2*)(sS + (row + 8) * 68 + col) = make_float2(s[nt][2], s[nt][3]);
            }
        }
        __syncthreads();

        // Parallel online softmax: 4 threads/row, 16 cols each
        {
            int r  = t >> 2;
            int c0 = (t & 3) * 16;
            float mo = rm[r];
            float mx = mo;
            #pragma unroll
            for (int j = 0; j < 16; j++) mx = fmaxf(mx, sS[r * 68 + c0 + j]);
            mx = fmaxf(mx, __shfl_xor_sync(0xffffffffu, mx, 1));
            mx = fmaxf(mx, __shfl_xor_sync(0xffffffffu, mx, 2));
            float sum = 0.f;
            #pragma unroll
            for (int j = 0; j < 16; j++) {
                float e = __expf(sS[r * 68 + c0 + j] - mx);
                sum += e;
                __nv_bfloat16 hh, ll;
                split2(e, hh, ll);
                sPh[r * ASTR + c0 + j] = __bfloat16_as_ushort(hh);
                sPl[r * ASTR + c0 + j] = __bfloat16_as_ushort(ll);
            }
            sum += __shfl_xor_sync(0xffffffffu, sum, 1);
            sum += __shfl_xor_sync(0xffffffffu, sum, 2);
            if ((t & 3) == 0) {
                float f = __expf(mo - mx);
                rf[r] = f;
                rl[r] = rl[r] * f + sum;
                rm[r] = mx;
            }
        }
        __syncthreads();

        // Rescale O, then O += P · V
        {
            float f0 = rf[wm * 16 + (lane >> 2)];
            float f1 = rf[wm * 16 + (lane >> 2) + 8];
            #pragma unroll
            for (int nt = 0; nt < 4; nt++) {
                accO[nt][0] *= f0; accO[nt][1] *= f0;
                accO[nt][2] *= f1; accO[nt][3] *= f1;
            }
        }
        #pragma unroll
        for (int ks = 0; ks < 4; ks++) {
            const int kbyte = ks * 32;
            uint32_t ph[4], pl[4], bhv[2][4], blv[2][4];
            {
                uint32_t off = (uint32_t)((wm * 16 + arow) * ASTR) * 2 + kbyte + acolb;
                ldmx4(ph, uPh + off);
                ldmx4(pl, uPl + off);
            }
            #pragma unroll
            for (int nt2 = 0; nt2 < 2; nt2++) {
                uint32_t off = (uint32_t)((wn * 32 + nt2 * 16 + brow) * ASTR) * 2
                             + kbyte + bcolb;
                ldmx4(bhv[nt2], uVh + off);
                ldmx4(blv[nt2], uVl + off);
            }
            #pragma unroll
            for (int nt = 0; nt < 4; nt++) {
                uint32_t b0h = bhv[nt >> 1][(nt & 1) * 2];
                uint32_t b1h = bhv[nt >> 1][(nt & 1) * 2 + 1];
                uint32_t b0l = blv[nt >> 1][(nt & 1) * 2];
                uint32_t b1l = blv[nt >> 1][(nt & 1) * 2 + 1];
                mma_bf16(accO[nt], ph, b0h, b1h);
                mma_bf16(accO[nt], ph, b0l, b1l);
                mma_bf16(accO[nt], pl, b0h, b1h);
            }
        }
        __syncthreads();
    }

    // Epilogue: normalize, exact GELU, stage, packed transposed writeback
    {
        int row0 = wm * 16 + (lane >> 2);
        float i0 = 1.f / rl[row0];
        float i1 = 1.f / rl[row0 + 8];
        #pragma unroll
        for (int nt = 0; nt < 4; nt++) {
            int col = wn * 32 + nt * 8 + (lane & 3) * 2;
            #pragma unroll
            for (int e = 0; e < 4; e++) {
                float v = accO[nt][e] * (e < 2 ? i0 : i1);
                float g = 0.5f * v * (1.f + erff(v * 0.70710678118654752f));
                sS[(row0 + (e >> 1) * 8) * 68 + col + (e & 1)] = g;
            }
        }
    }
    __syncthreads();
    for (int idx = t; idx < 4096; idx += 256) {
        int d = idx >> 6, qi = idx & 63;
        ob[(size_t)d * NPIX + q0 + qi] = packsplit(sS[qi * 68 + d]);
    }
}

// ---------------------------------------------------------------------------
extern "C" void kernel_launch(void* const* d_in, const int* in_sizes, int n_in,
                              void* d_out, int out_size)
{
    const float* x    = (const float*)d_in[0];  // [8,256,32,32]
    const float* Wq   = (const float*)d_in[1];  // [512,256,1,1]
    const float* Wkv  = (const float*)d_in[2];  // [1024,256,3,3]
    const float* Wout = (const float*)d_in[3];  // [256,512,1,1]
    const float* bout = (const float*)d_in[4];  // [256]
    float* out = (float*)d_out;                 // [8,256,32,32]

    uint32_t *wqp, *wkvp, *wop, *xp, *qp, *kvp, *aop;
    cudaGetSymbolAddress((void**)&wqp,  g_Wqp);
    cudaGetSymbolAddress((void**)&wkvp, g_Wkvp);
    cudaGetSymbolAddress((void**)&wop,  g_Wop);
    cudaGetSymbolAddress((void**)&xp,   g_Xp);
    cudaGetSymbolAddress((void**)&qp,   g_Qp);
    cudaGetSymbolAddress((void**)&kvp,  g_KVp);
    cudaGetSymbolAddress((void**)&aop,  g_AOp);

    dim3 blk(256);

    // 0) Split/pack weights and input (0.125 attention scale folded into Wq)
    split_pack4<<<(INNER * C_IN / 4 + 255) / 256, blk>>>(
        (const float4*)Wq, (uint4*)wqp, INNER * C_IN / 4, 0.125f);
    split_pack4<<<(MKV * KCONV / 4 + 255) / 256, blk>>>(
        (const float4*)Wkv, (uint4*)wkvp, MKV * KCONV / 4, 1.f);
    split_pack4<<<(C_IN * INNER / 4 + 255) / 256, blk>>>(
        (const float4*)Wout, (uint4*)wop, C_IN * INNER / 4, 1.f);
    split_pack4<<<(BATCH * C_IN * NPIX / 4 + 255) / 256, blk>>>(
        (const float4*)x, (uint4*)xp, BATCH * C_IN * NPIX / 4, 1.f);

    // 1) Q = (Wq*0.125) * x  -> packed   (M=512, N=1024, K=256, per batch)
    cudaFuncSetAttribute(gemm_mma<1>,
                         cudaFuncAttributeMaxDynamicSharedMemorySize, CONV_SMEM);
    gemm_mma<1><<<dim3(16, 4, BATCH), blk, CONV_SMEM>>>(
        wqp, xp, qp, nullptr, INNER, NPIX, C_IN);

    // 2) KV = conv3x3(x) -> packed  (M=1024, N=1024, K=2304, per batch)
    cudaFuncSetAttribute(conv3x3_mma,
                         cudaFuncAttributeMaxDynamicSharedMemorySize, CONV_SMEM);
    conv3x3_mma<<<dim3(16, 8, BATCH), blk, CONV_SMEM>>>(wkvp, xp, kvp);

    // 3) Flash attention + GELU -> packed
    cudaFuncSetAttribute(flash_attn_mma,
                         cudaFuncAttributeMaxDynamicSharedMemorySize, FA_SMEM);
    flash_attn_mma<<<dim3(16, BATCH * HEADS), blk, FA_SMEM>>>(qp, kvp, aop);

    // 4) out = Wout * gelu_attn + bout   (M=256, N=1024, K=512, per batch)
    cudaFuncSetAttribute(gemm_mma<0>,
                         cudaFuncAttributeMaxDynamicSharedMemorySize, CONV_SMEM);
    gemm_mma<0><<<dim3(16, 2, BATCH), blk, CONV_SMEM>>>(
        wop, aop, out, bout, 256, NPIX, INNER);
}

// round 13
// speedup vs baseline: 2.9756x; 1.4569x over previous
#include <cuda_runtime.h>
#include <cuda_bf16.h>
#include <cstdint>
#include <math.h>

// Problem constants
#define BATCH  8
#define C_IN   256
#define NPIX   1024   // 32*32
#define INNER  512
#define HEADS  8
#define DH     64
#define KCONV  2304   // 256*9
#define MKV    1024

// ---------------------------------------------------------------------------
// bf16 hi/lo PLANE format: value v ~ hi + lo, hi = bf16(v), lo = bf16(v - hi).
// hi and lo stored as separate bf16 arrays so every tile fill is a pure
// contiguous 16B copy (cp.async-able), ldmatrix-ready. ~2^-16 rel precision.
// ---------------------------------------------------------------------------
__device__ uint16_t g_Wq_h [(size_t)INNER * C_IN],  g_Wq_l [(size_t)INNER * C_IN];
__device__ uint16_t g_Wkv_h[(size_t)MKV * KCONV],   g_Wkv_l[(size_t)MKV * KCONV];
__device__ uint16_t g_Wo_h [(size_t)C_IN * INNER],  g_Wo_l [(size_t)C_IN * INNER];
__device__ uint16_t g_imT_h[(size_t)BATCH * NPIX * KCONV];  // im2col^T [b][pix][k]
__device__ uint16_t g_imT_l[(size_t)BATCH * NPIX * KCONV];
__device__ uint16_t g_XT_h [(size_t)BATCH * NPIX * C_IN];   // x^T [b][pix][ci]
__device__ uint16_t g_XT_l [(size_t)BATCH * NPIX * C_IN];
__device__ uint16_t g_QT_h [(size_t)BATCH * NPIX * INNER];  // Q^T [b][pix][hd]
__device__ uint16_t g_QT_l [(size_t)BATCH * NPIX * INNER];
__device__ uint16_t g_KT_h [(size_t)BATCH * NPIX * INNER];  // K^T [b][pix][hd]
__device__ uint16_t g_KT_l [(size_t)BATCH * NPIX * INNER];
__device__ uint16_t g_V_h  [(size_t)BATCH * INNER * NPIX];  // V   [b][hd][pix]
__device__ uint16_t g_V_l  [(size_t)BATCH * INNER * NPIX];
__device__ uint16_t g_AOT_h[(size_t)BATCH * NPIX * INNER];  // gelu(attn)^T [b][pix][hd]
__device__ uint16_t g_AOT_l[(size_t)BATCH * NPIX * INNER];

__device__ __forceinline__ void split2(float v, __nv_bfloat16& h, __nv_bfloat16& l) {
    h = __float2bfloat16(v);
    l = __float2bfloat16(v - __bfloat162float(h));
}
__device__ __forceinline__ uint16_t u16(__nv_bfloat16 x) { return __bfloat16_as_ushort(x); }

// ===========================================================================
// mma.sync / ldmatrix / cp.async helpers (plain sm_103 — tcgen05 is 'a'-only)
// ===========================================================================
__device__ __forceinline__ uint32_t smem_u32(const void* p) {
    uint32_t a;
    asm("{ .reg .u64 t; cvta.to.shared.u64 t, %1; cvt.u32.u64 %0, t; }"
        : "=r"(a) : "l"(p));
    return a;
}
__device__ __forceinline__ void ldmx4(uint32_t* r, uint32_t addr) {
    asm volatile("ldmatrix.sync.aligned.m8n8.x4.shared.b16 {%0,%1,%2,%3}, [%4];"
        : "=r"(r[0]), "=r"(r[1]), "=r"(r[2]), "=r"(r[3]) : "r"(addr));
}
__device__ __forceinline__ void mma_bf16(float* c, const uint32_t* a,
                                         uint32_t b0, uint32_t b1) {
    asm volatile(
        "mma.sync.aligned.m16n8k16.row.col.f32.bf16.bf16.f32 "
        "{%0,%1,%2,%3}, {%4,%5,%6,%7}, {%8,%9}, {%0,%1,%2,%3};"
        : "+f"(c[0]), "+f"(c[1]), "+f"(c[2]), "+f"(c[3])
        : "r"(a[0]), "r"(a[1]), "r"(a[2]), "r"(a[3]), "r"(b0), "r"(b1));
}
__device__ __forceinline__ void cp16(uint32_t dst, const void* src) {
    asm volatile("cp.async.cg.shared.global [%0], [%1], 16;" :: "r"(dst), "l"(src));
}
#define CP_COMMIT() asm volatile("cp.async.commit_group;")
#define CP_WAIT1()  asm volatile("cp.async.wait_group 1;")
#define CP_WAIT0()  asm volatile("cp.async.wait_group 0;")

#define ASTR 72   // smem row stride in halfwords (144B): conflict-free ldmatrix

// ===========================================================================
// split weights into planes
// ===========================================================================
__global__ __launch_bounds__(256)
void split_planes(const float* __restrict__ in, uint16_t* __restrict__ oh,
                  uint16_t* __restrict__ ol, int n, float scale)
{
    int i = blockIdx.x * 256 + threadIdx.x;
    if (i < n) {
        float v = in[i] * scale;
        __nv_bfloat16 h, l; split2(v, h, l);
        oh[i] = u16(h); ol[i] = u16(l);
    }
}

// ===========================================================================
// im2colT: x [b][256][32][32] fp32 -> imT planes [b][pix][2304] + XT [b][pix][256]
// Block = (py, b): stages 3 image rows x 256 ch in smem as split planes,
// then writes k-contiguous, warp-coalesced output rows.
// ===========================================================================
#define IM2_SMEM (2 * 256 * 3 * 32 * 2)   // 98304 B

__global__ __launch_bounds__(256)
void im2colT(const float* __restrict__ x,
             uint16_t* __restrict__ imTh, uint16_t* __restrict__ imTl,
             uint16_t* __restrict__ XTh,  uint16_t* __restrict__ XTl)
{
    extern __shared__ uint16_t s16[];
    uint16_t* sXh = s16;               // [256][3][32] : ci*96 + row*32 + px
    uint16_t* sXl = s16 + 24576;
    const int t  = threadIdx.x;
    const int py = blockIdx.x, b = blockIdx.y;
    const float* xb = x + (size_t)b * C_IN * NPIX;

    for (int row = 0; row < 3; row++) {
        int y = py - 1 + row;
        bool ok = (unsigned)y < 32u;
        #pragma unroll
        for (int r = 0; r < 8; r++) {
            int i = t + r * 256;
            int ci = i >> 3, q = i & 7;
            float4 v = ok ? *(const float4*)(xb + (size_t)ci * NPIX + y * 32 + q * 4)
                          : make_float4(0.f, 0.f, 0.f, 0.f);
            int o = ci * 96 + row * 32 + q * 4;
            __nv_bfloat16 h, l;
            split2(v.x, h, l); sXh[o + 0] = u16(h); sXl[o + 0] = u16(l);
            split2(v.y, h, l); sXh[o + 1] = u16(h); sXl[o + 1] = u16(l);
            split2(v.z, h, l); sXh[o + 2] = u16(h); sXl[o + 2] = u16(l);
            split2(v.w, h, l); sXh[o + 3] = u16(h); sXl[o + 3] = u16(l);
        }
    }
    __syncthreads();

    uint16_t* oh = imTh + ((size_t)b * NPIX + py * 32) * KCONV;
    uint16_t* ol = imTl + ((size_t)b * NPIX + py * 32) * KCONV;
    const int lane = t & 31, w = t >> 5;
    for (int pg = 0; pg < 4; pg++) {
        int px = pg * 8 + w;
        #pragma unroll 8
        for (int kk = 0; kk < 72; kk++) {
            int k   = kk * 32 + lane;
            int ci  = (k * 7282) >> 16;       // k/9 exact for k<2304
            int tap = k - ci * 9;
            int dy  = (tap * 22) >> 6;        // tap/3 exact for tap<9
            int dx  = tap - dy * 3;
            int xx  = px + dx - 1;
            uint16_t vh = 0, vl = 0;
            if ((unsigned)xx < 32u) {
                int o = ci * 96 + dy * 32 + xx;
                vh = sXh[o]; vl = sXl[o];
            }
            oh[(size_t)px * KCONV + k] = vh;
            ol[(size_t)px * KCONV + k] = vl;
        }
    }
    uint16_t* xh = XTh + ((size_t)b * NPIX + py * 32) * C_IN;
    uint16_t* xl = XTl + ((size_t)b * NPIX + py * 32) * C_IN;
    for (int i = t; i < 32 * 256; i += 256) {
        int px = i >> 8, ci = i & 255;
        xh[(size_t)px * C_IN + ci] = sXh[ci * 96 + 32 + px];
        xl[(size_t)px * C_IN + ci] = sXl[ci * 96 + 32 + px];
    }
}

// ===========================================================================
// Generic plane GEMM, cp.async double-buffered:
//   C[b][m][n] = sum_k A[m][k] * B[b][n][k]   (A,B bf16x3 planes, fp32 acc)
// CTA 128m x 64n, K panels of 64. EPI: 0 -> transposed planes [b][n][m] (QT);
// 1 -> KV mixed (m<512: KT planes; else V direct planes); 2 -> float + bias.
// ===========================================================================
#define GP_BUF  55296
#define GP_SMEM (2 * GP_BUF)   // 110592 B

#define GP_FILL(PANEL, BUF) do {                                               \
    const int k0_ = (PANEL) * 64;                                              \
    uint32_t ub_ = us + (BUF) * GP_BUF;                                        \
    _Pragma("unroll")                                                          \
    for (int r_ = 0; r_ < 8; r_++) {                                           \
        int c_ = t + r_ * 256;                                                 \
        int row_ = c_ >> 4, sub_ = c_ & 15, pl_ = sub_ >> 3, col_ = sub_ & 7;  \
        const uint16_t* s_ = (pl_ ? Al : Ah) + (size_t)(m0 + row_) * K + k0_ + col_ * 8; \
        cp16(ub_ + pl_ * 18432 + row_ * 144 + col_ * 16, s_);                  \
    }                                                                          \
    _Pragma("unroll")                                                          \
    for (int r_ = 0; r_ < 4; r_++) {                                           \
        int c_ = t + r_ * 256;                                                 \
        int row_ = c_ >> 4, sub_ = c_ & 15, pl_ = sub_ >> 3, col_ = sub_ & 7;  \
        const uint16_t* s_ = (pl_ ? Blb : Bhb) + (size_t)(n0 + row_) * K + k0_ + col_ * 8; \
        cp16(ub_ + 36864 + pl_ * 9216 + row_ * 144 + col_ * 16, s_);           \
    }                                                                          \
} while (0)

template<int EPI>
__global__ __launch_bounds__(256)
void gemm_planes(const uint16_t* __restrict__ Ah, const uint16_t* __restrict__ Al,
                 const uint16_t* __restrict__ Bh, const uint16_t* __restrict__ Bl,
                 int K,
                 uint16_t* __restrict__ Oth, uint16_t* __restrict__ Otl,
                 uint16_t* __restrict__ Ovh, uint16_t* __restrict__ Ovl,
                 float* __restrict__ Of, const float* __restrict__ bias, int M)
{
    extern __shared__ char smem[];
    const uint32_t us = smem_u32(smem);
    const int t = threadIdx.x;
    const int warp = t >> 5, lane = t & 31;
    const int wm = warp & 3, wn = warp >> 2;
    const int n0 = blockIdx.x * 64, m0 = blockIdx.y * 128;
    const int b  = blockIdx.z;
    const uint16_t* Bhb = Bh + (size_t)b * NPIX * K;
    const uint16_t* Blb = Bl + (size_t)b * NPIX * K;

    const int arow  = lane & 15;
    const int acolb = (lane >> 4) * 16;
    const int brow  = (lane & 7) + ((lane >> 4) << 3);
    const int bcolb = ((lane >> 3) & 1) * 16;

    const int NP = K >> 6;
    float acc[2][4][4] = {};

    GP_FILL(0, 0); CP_COMMIT();
    for (int p = 0; p < NP; p++) {
        if (p + 1 < NP) { GP_FILL(p + 1, (p + 1) & 1); CP_COMMIT(); CP_WAIT1(); }
        else            { CP_WAIT0(); }
        __syncthreads();
        uint32_t ub  = us + (p & 1) * GP_BUF;
        uint32_t uAh = ub, uAl = ub + 18432, uBh = ub + 36864, uBl = ub + 46080;
        #pragma unroll
        for (int ks = 0; ks < 4; ks++) {
            const int kb = ks * 32;
            uint32_t ah[2][4], al[2][4], bh[2][4], bl[2][4];
            #pragma unroll
            for (int mt = 0; mt < 2; mt++) {
                uint32_t off = (uint32_t)((wm * 32 + mt * 16 + arow) * ASTR) * 2
                             + kb + acolb;
                ldmx4(ah[mt], uAh + off);
                ldmx4(al[mt], uAl + off);
            }
            #pragma unroll
            for (int nt2 = 0; nt2 < 2; nt2++) {
                uint32_t off = (uint32_t)((wn * 32 + nt2 * 16 + brow) * ASTR) * 2
                             + kb + bcolb;
                ldmx4(bh[nt2], uBh + off);
                ldmx4(bl[nt2], uBl + off);
            }
            #pragma unroll
            for (int mt = 0; mt < 2; mt++)
                #pragma unroll
                for (int nt = 0; nt < 4; nt++) {
                    uint32_t b0h = bh[nt >> 1][(nt & 1) * 2];
                    uint32_t b1h = bh[nt >> 1][(nt & 1) * 2 + 1];
                    uint32_t b0l = bl[nt >> 1][(nt & 1) * 2];
                    uint32_t b1l = bl[nt >> 1][(nt & 1) * 2 + 1];
                    mma_bf16(acc[mt][nt], ah[mt], b0h, b1h);
                    mma_bf16(acc[mt][nt], ah[mt], b0l, b1l);
                    mma_bf16(acc[mt][nt], al[mt], b0h, b1h);
                }
        }
        __syncthreads();
    }

    // stage fp32 result, then epilogue-specific writeback
    float* sO = (float*)smem;   // [128][66]
    #pragma unroll
    for (int mt = 0; mt < 2; mt++)
        #pragma unroll
        for (int nt = 0; nt < 4; nt++) {
            int row = wm * 32 + mt * 16 + (lane >> 2);
            int col = wn * 32 + nt * 8 + (lane & 3) * 2;
            *(float2*)(sO + row * 66 + col) =
                make_float2(acc[mt][nt][0], acc[mt][nt][1]);
            *(float2*)(sO + (row + 8) * 66 + col) =
                make_float2(acc[mt][nt][2], acc[mt][nt][3]);
        }
    __syncthreads();

    if (EPI == 0 || (EPI == 1 && m0 < 512)) {
        // transposed planes [b][n][m], row length 512
        for (int i = t; i < 8192; i += 256) {
            int n = i >> 7, m = i & 127;
            __nv_bfloat16 h, l; split2(sO[m * 66 + n], h, l);
            size_t o = ((size_t)b * NPIX + n0 + n) * 512 + m0 + m;
            Oth[o] = u16(h); Otl[o] = u16(l);
        }
    } else if (EPI == 1) {
        // V direct planes [b][m-512][n]
        for (int i = t; i < 8192; i += 256) {
            int m = i >> 6, c = i & 63;
            __nv_bfloat16 h, l; split2(sO[m * 66 + c], h, l);
            size_t o = ((size_t)b * INNER + (m0 - 512 + m)) * NPIX + n0 + c;
            Ovh[o] = u16(h); Ovl[o] = u16(l);
        }
    } else {
        for (int i = t; i < 8192; i += 256) {
            int m = i >> 6, c = i & 63;
            Of[((size_t)b * M + m0 + m) * NPIX + n0 + c] = sO[m * 66 + c] + bias[m0 + m];
        }
    }
}

// ===========================================================================
// Flash attention, bf16x3 mma, cp.async prefetch (K and V in separate commit
// groups so K(t+1) fill overlaps softmax+PV(t), V(t+1) overlaps S(t+1)).
// Scale folded into Wq. Parallel softmax (4 thr/row). GELU fused. Writes AOT.
// ===========================================================================
#define FA_SMEM (8 * 9216 + 64 * 68 * 4 + 3 * 64 * 4)   // 91904 B

#define FA_FILLK(K0) do {                                                      \
    _Pragma("unroll")                                                          \
    for (int r_ = 0; r_ < 4; r_++) {                                           \
        int c_ = t + r_ * 256;                                                 \
        int row_ = c_ >> 4, sub_ = c_ & 15, pl_ = sub_ >> 3, col_ = sub_ & 7;  \
        cp16(uKh + pl_ * 9216 + row_ * 144 + col_ * 16,                        \
             (pl_ ? ksl : ksh) + (size_t)((K0) + row_) * INNER + col_ * 8);    \
    }                                                                          \
} while (0)
#define FA_FILLV(K0) do {                                                      \
    _Pragma("unroll")                                                          \
    for (int r_ = 0; r_ < 4; r_++) {                                           \
        int c_ = t + r_ * 256;                                                 \
        int row_ = c_ >> 4, sub_ = c_ & 15, pl_ = sub_ >> 3, col_ = sub_ & 7;  \
        cp16(uVh + pl_ * 9216 + row_ * 144 + col_ * 16,                        \
             (pl_ ? vsl : vsh) + (size_t)row_ * NPIX + (K0) + col_ * 8);       \
    }                                                                          \
} while (0)

__global__ __launch_bounds__(256)
void flash_attn_mma(const uint16_t* __restrict__ QTh, const uint16_t* __restrict__ QTl,
                    const uint16_t* __restrict__ KTh, const uint16_t* __restrict__ KTl,
                    const uint16_t* __restrict__ Vh,  const uint16_t* __restrict__ Vl,
                    uint16_t* __restrict__ AOTh, uint16_t* __restrict__ AOTl)
{
    extern __shared__ char smc[];
    const uint32_t base = smem_u32(smc);
    const uint32_t uQh = base,         uQl = base + 9216;
    const uint32_t uKh = base + 18432, uKl = base + 27648;
    const uint32_t uVh = base + 36864, uVl = base + 46080;
    const uint32_t uPh = base + 55296, uPl = base + 64512;
    uint16_t* sPh = (uint16_t*)(smc + 55296);
    uint16_t* sPl = (uint16_t*)(smc + 64512);
    float* sS = (float*)(smc + 73728);   // [64][68]
    float* rm = sS + 64 * 68;
    float* rl = rm + 64;
    float* rf = rl + 64;

    const int t    = threadIdx.x;
    const int warp = t >> 5, lane = t & 31;
    const int wm   = warp & 3, wn = warp >> 2;
    const int q0   = blockIdx.x * 64;
    const int bh   = blockIdx.y;
    const int b    = bh >> 3, h = bh & 7;

    const uint16_t* qsh = QTh + ((size_t)b * NPIX + q0) * INNER + h * 64;
    const uint16_t* qsl = QTl + ((size_t)b * NPIX + q0) * INNER + h * 64;
    const uint16_t* ksh = KTh + (size_t)b * NPIX * INNER + h * 64;
    const uint16_t* ksl = KTl + (size_t)b * NPIX * INNER + h * 64;
    const uint16_t* vsh = Vh + ((size_t)b * INNER + h * 64) * NPIX;
    const uint16_t* vsl = Vl + ((size_t)b * INNER + h * 64) * NPIX;

    const int arow  = lane & 15;
    const int acolb = (lane >> 4) * 16;
    const int brow  = (lane & 7) + ((lane >> 4) << 3);
    const int bcolb = ((lane >> 3) & 1) * 16;

    // prologue: Q + K0 in one group, V0 in a second
    #pragma unroll
    for (int r = 0; r < 4; r++) {
        int c = t + r * 256;
        int row = c >> 4, sub = c & 15, pl = sub >> 3, col = sub & 7;
        cp16(uQh + pl * 9216 + row * 144 + col * 16,
             (pl ? qsl : qsh) + (size_t)row * INNER + col * 8);
    }
    FA_FILLK(0); CP_COMMIT();
    FA_FILLV(0); CP_COMMIT();
    if (t < 64) { rm[t] = -1e30f; rl[t] = 0.f; }

    float accO[4][4] = {};

    for (int kt = 0; kt < 16; kt++) {
        CP_WAIT1();            // Q + K_t complete
        __syncthreads();

        // S = Qs · K^T
        float s[4][4] = {};
        #pragma unroll
        for (int ks = 0; ks < 4; ks++) {
            const int kbyte = ks * 32;
            uint32_t ah[4], al[4], bhv[2][4], blv[2][4];
            {
                uint32_t off = (uint32_t)((wm * 16 + arow) * ASTR) * 2 + kbyte + acolb;
                ldmx4(ah, uQh + off);
                ldmx4(al, uQl + off);
            }
            #pragma unroll
            for (int nt2 = 0; nt2 < 2; nt2++) {
                uint32_t off = (uint32_t)((wn * 32 + nt2 * 16 + brow) * ASTR) * 2
                             + kbyte + bcolb;
                ldmx4(bhv[nt2], uKh + off);
                ldmx4(blv[nt2], uKl + off);
            }
            #pragma unroll
            for (int nt = 0; nt < 4; nt++) {
                uint32_t b0h = bhv[nt >> 1][(nt & 1) * 2];
                uint32_t b1h = bhv[nt >> 1][(nt & 1) * 2 + 1];
                uint32_t b0l = blv[nt >> 1][(nt & 1) * 2];
                uint32_t b1l = blv[nt >> 1][(nt & 1) * 2 + 1];
                mma_bf16(s[nt], ah, b0h, b1h);
                mma_bf16(s[nt], ah, b0l, b1l);
                mma_bf16(s[nt], al, b0h, b1h);
            }
        }
        {
            int row = wm * 16 + (lane >> 2);
            #pragma unroll
            for (int nt = 0; nt < 4; nt++) {
                int col = wn * 32 + nt * 8 + (lane & 3) * 2;
                *(float2*)(sS + row * 68 + col)       = make_float2(s[nt][0], s[nt][1]);
                *(float2*)(sS + (row + 8) * 68 + col) = make_float2(s[nt][2], s[nt][3]);
            }
        }
        __syncthreads();

        if (kt < 15) { FA_FILLK((kt + 1) * 64); CP_COMMIT(); }   // overlaps softmax+PV

        // parallel online softmax: 4 threads/row
        {
            int r  = t >> 2;
            int c0 = (t & 3) * 16;
            float mo = rm[r];
            float mx = mo;
            #pragma unroll
            for (int j = 0; j < 16; j++) mx = fmaxf(mx, sS[r * 68 + c0 + j]);
            mx = fmaxf(mx, __shfl_xor_sync(0xffffffffu, mx, 1));
            mx = fmaxf(mx, __shfl_xor_sync(0xffffffffu, mx, 2));
            float sum = 0.f;
            #pragma unroll
            for (int j = 0; j < 16; j++) {
                float e = __expf(sS[r * 68 + c0 + j] - mx);
                sum += e;
                __nv_bfloat16 hh, ll; split2(e, hh, ll);
                sPh[r * ASTR + c0 + j] = u16(hh);
                sPl[r * ASTR + c0 + j] = u16(ll);
            }
            sum += __shfl_xor_sync(0xffffffffu, sum, 1);
            sum += __shfl_xor_sync(0xffffffffu, sum, 2);
            if ((t & 3) == 0) {
                float f = __expf(mo - mx);
                rf[r] = f;
                rl[r] = rl[r] * f + sum;
                rm[r] = mx;
            }
        }
        if (kt < 15) { CP_WAIT1(); } else { CP_WAIT0(); }   // V_t complete
        __syncthreads();                                    // P + V visible

        // rescale O, O += P · V
        {
            float f0 = rf[wm * 16 + (lane >> 2)];
            float f1 = rf[wm * 16 + (lane >> 2) + 8];
            #pragma unroll
            for (int nt = 0; nt < 4; nt++) {
                accO[nt][0] *= f0; accO[nt][1] *= f0;
                accO[nt][2] *= f1; accO[nt][3] *= f1;
            }
        }
        #pragma unroll
        for (int ks = 0; ks < 4; ks++) {
            const int kbyte = ks * 32;
            uint32_t ph[4], pl[4], bhv[2][4], blv[2][4];
            {
                uint32_t off = (uint32_t)((wm * 16 + arow) * ASTR) * 2 + kbyte + acolb;
                ldmx4(ph, uPh + off);
                ldmx4(pl, uPl + off);
            }
            #pragma unroll
            for (int nt2 = 0; nt2 < 2; nt2++) {
                uint32_t off = (uint32_t)((wn * 32 + nt2 * 16 + brow) * ASTR) * 2
                             + kbyte + bcolb;
                ldmx4(bhv[nt2], uVh + off);
                ldmx4(blv[nt2], uVl + off);
            }
            #pragma unroll
            for (int nt = 0; nt < 4; nt++) {
                uint32_t b0h = bhv[nt >> 1][(nt & 1) * 2];
                uint32_t b1h = bhv[nt >> 1][(nt & 1) * 2 + 1];
                uint32_t b0l = blv[nt >> 1][(nt & 1) * 2];
                uint32_t b1l = blv[nt >> 1][(nt & 1) * 2 + 1];
                mma_bf16(accO[nt], ph, b0h, b1h);
                mma_bf16(accO[nt], ph, b0l, b1l);
                mma_bf16(accO[nt], pl, b0h, b1h);
            }
        }
        __syncthreads();
        if (kt < 15) { FA_FILLV((kt + 1) * 64); CP_COMMIT(); }   // overlaps S(t+1)
    }

    // epilogue: normalize, exact GELU, stage, write AOT planes
    {
        int row0 = wm * 16 + (lane >> 2);
        float i0 = 1.f / rl[row0];
        float i1 = 1.f / rl[row0 + 8];
        #pragma unroll
        for (int nt = 0; nt < 4; nt++) {
            int col = wn * 32 + nt * 8 + (lane & 3) * 2;
            #pragma unroll
            for (int e = 0; e < 4; e++) {
                float v = accO[nt][e] * (e < 2 ? i0 : i1);
                float g = 0.5f * v * (1.f + erff(v * 0.70710678118654752f));
                sS[(row0 + (e >> 1) * 8) * 68 + col + (e & 1)] = g;
            }
        }
    }
    __syncthreads();
    for (int idx = t; idx < 4096; idx += 256) {
        int q = idx >> 6, d = idx & 63;
        __nv_bfloat16 hh, ll; split2(sS[q * 68 + d], hh, ll);
        size_t o = ((size_t)b * NPIX + q0 + q) * INNER + h * 64 + d;
        AOTh[o] = u16(hh); AOTl[o] = u16(ll);
    }
}

// ---------------------------------------------------------------------------
extern "C" void kernel_launch(void* const* d_in, const int* in_sizes, int n_in,
                              void* d_out, int out_size)
{
    const float* x    = (const float*)d_in[0];
    const float* Wq   = (const float*)d_in[1];
    const float* Wkv  = (const float*)d_in[2];
    const float* Wout = (const float*)d_in[3];
    const float* bout = (const float*)d_in[4];
    float* out = (float*)d_out;

    uint16_t *wqh, *wql, *wkvh, *wkvl, *woh, *wol;
    uint16_t *imh, *iml, *xth, *xtl, *qth, *qtl, *kth, *ktl, *vh, *vl, *aoh, *aol;
    cudaGetSymbolAddress((void**)&wqh,  g_Wq_h);  cudaGetSymbolAddress((void**)&wql,  g_Wq_l);
    cudaGetSymbolAddress((void**)&wkvh, g_Wkv_h); cudaGetSymbolAddress((void**)&wkvl, g_Wkv_l);
    cudaGetSymbolAddress((void**)&woh,  g_Wo_h);  cudaGetSymbolAddress((void**)&wol,  g_Wo_l);
    cudaGetSymbolAddress((void**)&imh,  g_imT_h); cudaGetSymbolAddress((void**)&iml,  g_imT_l);
    cudaGetSymbolAddress((void**)&xth,  g_XT_h);  cudaGetSymbolAddress((void**)&xtl,  g_XT_l);
    cudaGetSymbolAddress((void**)&qth,  g_QT_h);  cudaGetSymbolAddress((void**)&qtl,  g_QT_l);
    cudaGetSymbolAddress((void**)&kth,  g_KT_h);  cudaGetSymbolAddress((void**)&ktl,  g_KT_l);
    cudaGetSymbolAddress((void**)&vh,   g_V_h);   cudaGetSymbolAddress((void**)&vl,   g_V_l);
    cudaGetSymbolAddress((void**)&aoh,  g_AOT_h); cudaGetSymbolAddress((void**)&aol,  g_AOT_l);

    dim3 blk(256);

    // 0) weight planes (0.125 folded into Wq) + im2colT / XT
    split_planes<<<(INNER * C_IN + 255) / 256, blk>>>(Wq, wqh, wql, INNER * C_IN, 0.125f);
    split_planes<<<(MKV * KCONV + 255) / 256, blk>>>(Wkv, wkvh, wkvl, MKV * KCONV, 1.f);
    split_planes<<<(C_IN * INNER + 255) / 256, blk>>>(Wout, woh, wol, C_IN * INNER, 1.f);
    cudaFuncSetAttribute(im2colT, cudaFuncAttributeMaxDynamicSharedMemorySize, IM2_SMEM);
    im2colT<<<dim3(32, BATCH), blk, IM2_SMEM>>>(x, imh, iml, xth, xtl);

    // 1) Q^T = (Wq/8 · x)^T   (K=256)
    cudaFuncSetAttribute(gemm_planes<0>, cudaFuncAttributeMaxDynamicSharedMemorySize, GP_SMEM);
    gemm_planes<0><<<dim3(16, 4, BATCH), blk, GP_SMEM>>>(
        wqh, wql, xth, xtl, C_IN, qth, qtl, nullptr, nullptr, nullptr, nullptr, INNER);

    // 2) KV = Wkv · im2col(x)  (K=2304): K-half -> KT planes, V-half -> V planes
    cudaFuncSetAttribute(gemm_planes<1>, cudaFuncAttributeMaxDynamicSharedMemorySize, GP_SMEM);
    gemm_planes<1><<<dim3(16, 8, BATCH), blk, GP_SMEM>>>(
        wkvh, wkvl, imh, iml, KCONV, kth, ktl, vh, vl, nullptr, nullptr, MKV);

    // 3) attention + GELU -> AOT planes
    cudaFuncSetAttribute(flash_attn_mma, cudaFuncAttributeMaxDynamicSharedMemorySize, FA_SMEM);
    flash_attn_mma<<<dim3(16, BATCH * HEADS), blk, FA_SMEM>>>(
        qth, qtl, kth, ktl, vh, vl, aoh, aol);

    // 4) out = Wout · gelu_attn + bout  (K=512)
    cudaFuncSetAttribute(gemm_planes<2>, cudaFuncAttributeMaxDynamicSharedMemorySize, GP_SMEM);
    gemm_planes<2><<<dim3(16, 2, BATCH), blk, GP_SMEM>>>(
        woh, wol, aoh, aol, INNER, nullptr, nullptr, nullptr, nullptr, out, bout, 256);
}